// round 13
// baseline (speedup 1.0000x reference)
#include <cuda_runtime.h>
#include <cuda_bf16.h>
#include <math.h>
#include <stdint.h>

#define DIM   2048
#define SEQ   3072
#define NH    16
#define HD    128
#define RANK  16
#define EPS_  1e-6f

// ---------------- scratch (static device memory; no allocs) ----------------
__device__ __nv_bfloat16 g_xhi[SEQ * DIM];
__device__ __nv_bfloat16 g_xlo[SEQ * DIM];
__device__ __nv_bfloat16 g_whi[4][DIM * DIM];
__device__ __nv_bfloat16 g_wlo[4][DIM * DIM];
__device__ __nv_bfloat16 g_qhi[SEQ * DIM];
__device__ __nv_bfloat16 g_qlo[SEQ * DIM];
__device__ __nv_bfloat16 g_khi[SEQ * DIM];
__device__ __nv_bfloat16 g_klo[SEQ * DIM];
__device__ __nv_bfloat16 g_vthi[NH * HD * SEQ];
__device__ __nv_bfloat16 g_vtlo[NH * HD * SEQ];
__device__ __nv_bfloat16 g_ohi[SEQ * DIM];
__device__ __nv_bfloat16 g_olo[SEQ * DIM];
__device__ float g_q[SEQ * DIM];
__device__ float g_k[SEQ * DIM];
__device__ float g_v[SEQ * DIM];

// ---------------- PTX helpers ---------------------------------------------
__device__ __forceinline__ uint32_t smem_u32(const void* p)
{
    uint32_t a;
    asm("{ .reg .u64 t; cvta.to.shared.u64 t, %1; cvt.u32.u64 %0, t; }"
        : "=r"(a) : "l"(p));
    return a;
}

__device__ __forceinline__ void bulk_g2s(uint32_t dst, const void* src,
                                         uint32_t bytes, uint32_t mbar)
{
    asm volatile(
        "cp.async.bulk.shared::cluster.global.mbarrier::complete_tx::bytes "
        "[%0], [%1], %2, [%3];"
        :: "r"(dst), "l"(src), "r"(bytes), "r"(mbar) : "memory");
}

__device__ __forceinline__ void mbar_init(uint32_t mbar, uint32_t cnt)
{
    asm volatile("mbarrier.init.shared.b64 [%0], %1;" :: "r"(mbar), "r"(cnt) : "memory");
}

__device__ __forceinline__ void mbar_expect(uint32_t mbar, uint32_t tx)
{
    asm volatile("mbarrier.arrive.expect_tx.shared.b64 _, [%0], %1;"
                 :: "r"(mbar), "r"(tx) : "memory");
}

__device__ __forceinline__ void mbar_wait(uint32_t mbar, uint32_t parity)
{
    asm volatile(
        "{\n\t"
        ".reg .pred P;\n\t"
        "LAB_%=:\n\t"
        "mbarrier.try_wait.parity.acquire.cta.shared::cta.b64 P, [%0], %1, 0x989680;\n\t"
        "@P bra DONE_%=;\n\t"
        "bra LAB_%=;\n\t"
        "DONE_%=:\n\t"
        "}"
        :: "r"(mbar), "r"(parity) : "memory");
}

__device__ __forceinline__ void ldsm_x4(uint32_t addr, uint32_t& r0, uint32_t& r1,
                                        uint32_t& r2, uint32_t& r3)
{
    asm volatile("ldmatrix.sync.aligned.m8n8.x4.shared.b16 {%0,%1,%2,%3}, [%4];"
                 : "=r"(r0), "=r"(r1), "=r"(r2), "=r"(r3) : "r"(addr));
}

__device__ __forceinline__ void mma_bf16(float* c,
                                         const uint32_t* a, uint32_t b0, uint32_t b1)
{
    asm volatile(
        "mma.sync.aligned.m16n8k16.row.col.f32.bf16.bf16.f32 "
        "{%0,%1,%2,%3}, {%4,%5,%6,%7}, {%8,%9}, {%0,%1,%2,%3};"
        : "+f"(c[0]), "+f"(c[1]), "+f"(c[2]), "+f"(c[3])
        : "r"(a[0]), "r"(a[1]), "r"(a[2]), "r"(a[3]), "r"(b0), "r"(b1));
}

// ---------------- batched param structs ------------------------------------
struct PrepBatch {
    const float* w[4];
    const float* ld[4];
    const float* lu[4];
    __nv_bfloat16* hi[4];
    __nv_bfloat16* lo[4];
};

struct GemmBatch {
    const __nv_bfloat16* bh[3];
    const __nv_bfloat16* bl[3];
    const float* bias[3];
    float* out[3];
};

struct NormBatch {
    const float* X[2];
    const float* w[2];
    __nv_bfloat16* hi[2];
    __nv_bfloat16* lo[2];
    float outscale[2];
};

// ---------------- 1) effective weight prep + bf16 split (batched) ----------
__global__ __launch_bounds__(256) void prep_weff_split(PrepBatch P, float scale)
{
    const int z  = blockIdx.z;
    const int kx = blockIdx.x * 256 + threadIdx.x;
    const int j  = blockIdx.y;
    const float* lu = P.lu[z];
    const float* ld = P.ld[z];
    float acc = 0.f;
#pragma unroll
    for (int r = 0; r < RANK; r++)
        acc += lu[j * RANK + r] * ld[r * DIM + kx];
    float v = P.w[z][j * DIM + kx] + scale * acc;
    __nv_bfloat16 h = __float2bfloat16(v);
    P.hi[z][j * DIM + kx] = h;
    P.lo[z][j * DIM + kx] = __float2bfloat16(v - __bfloat162float(h));
}

// ---------------- 2) fp32 -> bf16 hi/lo split -------------------------------
__global__ __launch_bounds__(256) void split_bf16(const float* __restrict__ in,
                                                  __nv_bfloat16* __restrict__ hi,
                                                  __nv_bfloat16* __restrict__ lo,
                                                  int n)
{
    int i = blockIdx.x * 256 + threadIdx.x;
    if (i < n) {
        float v = in[i];
        __nv_bfloat16 h = __float2bfloat16(v);
        hi[i] = h;
        lo[i] = __float2bfloat16(v - __bfloat162float(h));
    }
}

// ---------------- 3) HMMA split-bf16 NT GEMM (bulk-async loads) -------------
// 128x128 tile, 256 threads, 2-stage, 2 CTA/SM. Loads via cp.async.bulk+mbarrier.
// smem: [0,16) mbar0/mbar1 | [128 ...) 2 stages x 40960 (4 tiles x 128 rows x 80B)
#define KC        32
#define ROWB      80
#define TILEB     (128 * ROWB)             // 10240
#define STAGEB    (4 * TILEB)              // 40960
#define GEMM_SMEM (128 + 2 * STAGEB)       // 82048 -> 2 CTA/SM

__global__ __launch_bounds__(256) void gemm_hmma(const __nv_bfloat16* __restrict__ Ahi,
                                                 const __nv_bfloat16* __restrict__ Alo,
                                                 GemmBatch P)
{
    extern __shared__ __align__(128) char sm[];
    const uint32_t sbase = smem_u32(sm);

    const int tid  = threadIdx.x;
    const int wid  = tid >> 5;
    const int lane = tid & 31;
    const int zz = blockIdx.z;
    const int m0 = blockIdx.y * 128;
    const int n0 = blockIdx.x * 128;
    const int wm = wid & 3;
    const int wn = wid >> 2;

    const __nv_bfloat16* Bhi = P.bh[zz];
    const __nv_bfloat16* Blo = P.bl[zz];
    const float* bias = P.bias[zz];
    float* C = P.out[zz];

    // per-thread bulk-copy assignment: op1 = A tiles, op2 = B tiles
    const int r1 = tid & 127;
    const __nv_bfloat16* s1 = (tid < 128)
        ? Ahi + (size_t)(m0 + r1) * DIM : Alo + (size_t)(m0 + r1) * DIM;
    const __nv_bfloat16* s2 = (tid < 128)
        ? Bhi + (size_t)(n0 + r1) * DIM : Blo + (size_t)(n0 + r1) * DIM;
    const uint32_t d1 = 128u + (tid < 128 ? 0u : (uint32_t)TILEB) + (uint32_t)r1 * ROWB;
    const uint32_t d2 = 128u + (tid < 128 ? 2u * TILEB : 3u * TILEB) + (uint32_t)r1 * ROWB;

    if (tid == 0) { mbar_init(sbase, 1); mbar_init(sbase + 8, 1); }
    __syncthreads();

    float acc[2][8][4];
#pragma unroll
    for (int i = 0; i < 2; i++)
#pragma unroll
        for (int j = 0; j < 8; j++)
#pragma unroll
            for (int e = 0; e < 4; e++) acc[i][j][e] = 0.f;

    const int NCH = DIM / KC;   // 64

    auto issue = [&](int c) {
        const uint32_t stg = (uint32_t)(c & 1) * STAGEB;
        const uint32_t mb = sbase + (uint32_t)(c & 1) * 8;
        if (tid == 0) mbar_expect(mb, 4u * 128u * 64u);
        bulk_g2s(sbase + stg + d1, s1 + c * KC, 64, mb);
        bulk_g2s(sbase + stg + d2, s2 + c * KC, 64, mb);
    };

    issue(0);
    issue(1);

    const uint32_t lrow16 = (uint32_t)(lane & 15);
    const uint32_t lhalf  = (uint32_t)(lane >> 4) * 16;

    for (int c = 0; c < NCH; c++) {
        mbar_wait(sbase + (uint32_t)(c & 1) * 8, (uint32_t)((c >> 1) & 1));

        const uint32_t st = sbase + 128 + (uint32_t)(c & 1) * STAGEB;
        const uint32_t aRow = st + (uint32_t)(wm * 32) * ROWB;
        const uint32_t bRow = st + 2 * TILEB + (uint32_t)(wn * 64) * ROWB;

#pragma unroll
        for (int ks = 0; ks < 2; ks++) {
            const uint32_t kb = (uint32_t)(ks * 32) + lhalf;

            uint32_t ah[2][4], al[2][4];
#pragma unroll
            for (int im = 0; im < 2; im++) {
                uint32_t ra = aRow + (im * 16 + lrow16) * ROWB + kb;
                ldsm_x4(ra,         ah[im][0], ah[im][1], ah[im][2], ah[im][3]);
                ldsm_x4(ra + TILEB, al[im][0], al[im][1], al[im][2], al[im][3]);
            }

#pragma unroll
            for (int in4 = 0; in4 < 4; in4++) {
                uint32_t rb = bRow + (in4 * 16 + lrow16) * ROWB + kb;
                uint32_t bh0, bh1, bh2, bh3, bl0, bl1, bl2, bl3;
                ldsm_x4(rb,         bh0, bh1, bh2, bh3);
                ldsm_x4(rb + TILEB, bl0, bl1, bl2, bl3);

#pragma unroll
                for (int im = 0; im < 2; im++) {
                    float* c0 = acc[im][in4 * 2];
                    float* c1 = acc[im][in4 * 2 + 1];
                    mma_bf16(c0, ah[im], bh0, bh2);
                    mma_bf16(c1, ah[im], bh1, bh3);
                    mma_bf16(c0, ah[im], bl0, bl2);
                    mma_bf16(c1, ah[im], bl1, bl3);
                    mma_bf16(c0, al[im], bh0, bh2);
                    mma_bf16(c1, al[im], bh1, bh3);
                }
            }
        }
        __syncthreads();
        if (c + 2 < NCH) issue(c + 2);
    }

    const int r0 = lane >> 2;
    const int cpair = (lane & 3) * 2;
#pragma unroll
    for (int im = 0; im < 2; im++) {
        const int mrow = m0 + wm * 32 + im * 16 + r0;
#pragma unroll
        for (int jn = 0; jn < 8; jn++) {
            const int col = n0 + wn * 64 + jn * 8 + cpair;
            const float b0 = bias[col], b1 = bias[col + 1];
            float* p0 = C + (size_t)mrow * DIM + col;
            float* p1 = C + (size_t)(mrow + 8) * DIM + col;
            *(float2*)p0 = make_float2(acc[im][jn][0] + b0, acc[im][jn][1] + b1);
            *(float2*)p1 = make_float2(acc[im][jn][2] + b0, acc[im][jn][3] + b1);
        }
    }
}

// ---------------- 4) RMSNorm + RoPE + bf16 hi/lo split (batched q/k) -------
__global__ __launch_bounds__(256) void rmsnorm_rope_split(NormBatch P,
                                                          const float* __restrict__ fcos,
                                                          const float* __restrict__ fsin)
{
    const int z = blockIdx.y;
    const int s = blockIdx.x;
    const int tid = threadIdx.x;
    __shared__ float red[256];

    const float* row = P.X[z] + (size_t)s * DIM;
    const float* w = P.w[z];
    __nv_bfloat16* hi = P.hi[z];
    __nv_bfloat16* lo = P.lo[z];
    const float outscale = P.outscale[z];

    float ss = 0.f;
#pragma unroll
    for (int i = tid; i < DIM; i += 256) { float v = row[i]; ss += v * v; }
    red[tid] = ss;
    __syncthreads();
    for (int st = 128; st > 0; st >>= 1) {
        if (tid < st) red[tid] += red[tid + st];
        __syncthreads();
    }
    const float rs = rsqrtf(red[0] / (float)DIM + EPS_);

#pragma unroll
    for (int p = tid; p < DIM / 2; p += 256) {
        int hp = p & 63;
        float c  = fcos[s * HD + 2 * hp];
        float sn = fsin[s * HD + 2 * hp + 1];
        float x1 = row[2 * p]     * rs * w[2 * p];
        float x2 = row[2 * p + 1] * rs * w[2 * p + 1];
        float e = (x1 * c - x2 * sn) * outscale;
        float o = (x1 * sn + x2 * c) * outscale;
        __nv_bfloat16 eh = __float2bfloat16(e);
        __nv_bfloat16 oh = __float2bfloat16(o);
        hi[(size_t)s * DIM + 2 * p]     = eh;
        hi[(size_t)s * DIM + 2 * p + 1] = oh;
        lo[(size_t)s * DIM + 2 * p]     = __float2bfloat16(e - __bfloat162float(eh));
        lo[(size_t)s * DIM + 2 * p + 1] = __float2bfloat16(o - __bfloat162float(oh));
    }
}

// ---------------- 5) V transpose + split: [s][h*128+d] -> [h][d][s] --------
__global__ __launch_bounds__(256) void vtrans_split(const float* __restrict__ V,
                                                    __nv_bfloat16* __restrict__ vthi,
                                                    __nv_bfloat16* __restrict__ vtlo)
{
    __shared__ float t[32][33];
    const int s0 = blockIdx.x * 32;
    const int d0 = blockIdx.y * 32;
    const int h  = blockIdx.z;
    const int tx = threadIdx.x;
    const int ty = threadIdx.y;

    for (int i = ty; i < 32; i += 8)
        t[i][tx] = V[(size_t)(s0 + i) * DIM + h * HD + d0 + tx];
    __syncthreads();
    for (int i = ty; i < 32; i += 8) {
        float v = t[tx][i];
        __nv_bfloat16 hv = __float2bfloat16(v);
        size_t idx = (size_t)h * HD * SEQ + (size_t)(d0 + i) * SEQ + s0 + tx;
        vthi[idx] = hv;
        vtlo[idx] = __float2bfloat16(v - __bfloat162float(hv));
    }
}

// ---------------- 6) tensor-core flash attention (bulk-async loads) --------
// CTA: 128 q-rows x 1 head, 256 threads = 8 warps, warp = 16 q-rows.
#define FA_KB   0
#define FA_VB   69632
#define FA_SS   143360
#define FA_PH   178176
#define FA_PL   196608
#define FA_MM   215040
#define FA_LL   215552
#define FA_AA   216064
#define FA_MB   216576
#define FA_SMEM 216640
#define KROWB   272
#define VROWB   144
#define NKT     (SEQ / 64)

__global__ __launch_bounds__(256, 1) void flash_attn_tc(
    const __nv_bfloat16* __restrict__ qhi, const __nv_bfloat16* __restrict__ qlo,
    const __nv_bfloat16* __restrict__ khi, const __nv_bfloat16* __restrict__ klo,
    const __nv_bfloat16* __restrict__ vthi, const __nv_bfloat16* __restrict__ vtlo,
    __nv_bfloat16* __restrict__ ohi, __nv_bfloat16* __restrict__ olo)
{
    extern __shared__ __align__(128) char sm[];
    const uint32_t sb = smem_u32(sm);
    const int tid  = threadIdx.x;
    const int wid  = tid >> 5;
    const int lane = tid & 31;
    const int qt = blockIdx.x;
    const int h  = blockIdx.y;
    const uint32_t lrow16 = (uint32_t)(lane & 15);
    const uint32_t lhalf  = (uint32_t)(lane >> 4) * 16;
    const int r0 = lane >> 2;
    const int c2 = (lane & 3) * 2;

    float* smM = (float*)(sm + FA_MM);
    float* smL = (float*)(sm + FA_LL);
    float* smA = (float*)(sm + FA_AA);

    // per-thread bulk-copy assignment
    //   tid <128: K row (hi if tid<64 else lo, row tid&63, 256B)  +  V lo row tid (128B)
    //   tid>=128: V hi row (tid-128) (128B)
    const __nv_bfloat16* kSrc = ((tid < 64) ? khi : klo)
        + (size_t)(tid & 63) * DIM + h * HD;
    const uint32_t kDst = FA_KB + (tid >= 64 ? 17408u : 0u) + (uint32_t)(tid & 63) * KROWB;
    const __nv_bfloat16* vSrc = (tid < 128)
        ? vtlo + (size_t)h * HD * SEQ + (size_t)tid * SEQ
        : vthi + (size_t)h * HD * SEQ + (size_t)(tid - 128) * SEQ;
    const uint32_t vDst = FA_VB + (tid < 128 ? 18432u : 0u)
        + (uint32_t)(tid & 127) * VROWB;

    if (tid == 0) { mbar_init(sb + FA_MB, 1); mbar_init(sb + FA_MB + 8, 1); }
    __syncthreads();

    auto issue = [&](int kt) {
        const uint32_t mb = sb + FA_MB + (uint32_t)(kt & 1) * 8;
        if (tid == 0) mbar_expect(mb, 65536u);
        if (tid < 128) {
            bulk_g2s(sb + kDst + (uint32_t)(kt & 1) * 34816u,
                     kSrc + (size_t)kt * 64 * DIM, 256, mb);
            bulk_g2s(sb + vDst + (uint32_t)(kt & 1) * 36864u,
                     vSrc + kt * 64, 128, mb);
        } else {
            bulk_g2s(sb + vDst + (uint32_t)(kt & 1) * 36864u,
                     vSrc + kt * 64, 128, mb);
        }
    };

    issue(0);
    issue(1);

    // ---- stage Q (hi then lo) through FA_SS, hold fragments in registers --
    uint32_t qh[8][4], ql[8][4];
    const size_t qoff = (size_t)(qt * 128) * DIM + h * HD;
#pragma unroll
    for (int pass = 0; pass < 2; pass++) {
        const __nv_bfloat16* src = (pass == 0) ? (qhi + qoff) : (qlo + qoff);
        for (int c = tid; c < 2048; c += 256) {
            int row = c >> 4, o16 = c & 15;
            *(uint4*)(sm + FA_SS + row * KROWB + o16 * 16) =
                *(const uint4*)(src + (size_t)row * DIM + o16 * 8);
        }
        __syncthreads();
#pragma unroll
        for (int kk = 0; kk < 8; kk++) {
            uint32_t ra = sb + FA_SS + (wid * 16 + lrow16) * KROWB + kk * 32 + lhalf;
            if (pass == 0) ldsm_x4(ra, qh[kk][0], qh[kk][1], qh[kk][2], qh[kk][3]);
            else           ldsm_x4(ra, ql[kk][0], ql[kk][1], ql[kk][2], ql[kk][3]);
        }
        __syncthreads();
    }
    if (tid < 128) { smM[tid] = -1e30f; smL[tid] = 0.f; }

    float oa[16][4];
#pragma unroll
    for (int g = 0; g < 16; g++)
#pragma unroll
        for (int e = 0; e < 4; e++) oa[g][e] = 0.f;

    for (int kt = 0; kt < NKT; kt++) {
        mbar_wait(sb + FA_MB + (uint32_t)(kt & 1) * 8, (uint32_t)((kt >> 1) & 1));
        const uint32_t kbS = sb + FA_KB + (uint32_t)(kt & 1) * 34816;
        const uint32_t vbS = sb + FA_VB + (uint32_t)(kt & 1) * 36864;

        float s[8][4];
#pragma unroll
        for (int g = 0; g < 8; g++)
#pragma unroll
            for (int e = 0; e < 4; e++) s[g][e] = 0.f;

#pragma unroll
        for (int kk = 0; kk < 8; kk++) {
#pragma unroll
            for (int j = 0; j < 4; j++) {
                uint32_t ra = kbS + (j * 16 + lrow16) * KROWB + kk * 32 + lhalf;
                uint32_t kh0, kh1, kh2, kh3, kl0, kl1, kl2, kl3;
                ldsm_x4(ra,         kh0, kh1, kh2, kh3);
                ldsm_x4(ra + 17408, kl0, kl1, kl2, kl3);
                mma_bf16(s[j * 2],     qh[kk], kh0, kh2);
                mma_bf16(s[j * 2 + 1], qh[kk], kh1, kh3);
                mma_bf16(s[j * 2],     qh[kk], kl0, kl2);
                mma_bf16(s[j * 2 + 1], qh[kk], kl1, kl3);
                mma_bf16(s[j * 2],     ql[kk], kh0, kh2);
                mma_bf16(s[j * 2 + 1], ql[kk], kh1, kh3);
            }
        }
#pragma unroll
        for (int g = 0; g < 8; g++) {
            int col = (g >> 1) * 16 + (g & 1) * 8 + c2;
            int row = wid * 16 + r0;
            *(float2*)(sm + FA_SS + row * KROWB + col * 4)       = make_float2(s[g][0], s[g][1]);
            *(float2*)(sm + FA_SS + (row + 8) * KROWB + col * 4) = make_float2(s[g][2], s[g][3]);
        }
        __syncthreads();

        {
            const int row = tid >> 1, seg = tid & 1;
            const float* sr = (const float*)(sm + FA_SS + row * KROWB + seg * 128);
            float v[32];
#pragma unroll
            for (int i = 0; i < 8; i++) {
                float4 f = *(const float4*)(sr + i * 4);
                v[i * 4] = f.x; v[i * 4 + 1] = f.y; v[i * 4 + 2] = f.z; v[i * 4 + 3] = f.w;
            }
            float mloc = v[0];
#pragma unroll
            for (int i = 1; i < 32; i++) mloc = fmaxf(mloc, v[i]);
            mloc = fmaxf(mloc, __shfl_xor_sync(0xffffffffu, mloc, 1));
            const float mold = smM[row];
            const float mx = fmaxf(mold, mloc);
            const float alpha = __expf(mold - mx);
            float sum = 0.f;
            __nv_bfloat162* dh = (__nv_bfloat162*)(sm + FA_PH + row * VROWB + seg * 64);
            __nv_bfloat162* dl = (__nv_bfloat162*)(sm + FA_PL + row * VROWB + seg * 64);
#pragma unroll
            for (int i = 0; i < 16; i++) {
                float p0 = __expf(v[2 * i]     - mx);
                float p1 = __expf(v[2 * i + 1] - mx);
                sum += p0 + p1;
                __nv_bfloat16 h0 = __float2bfloat16(p0);
                __nv_bfloat16 h1 = __float2bfloat16(p1);
                dh[i] = __nv_bfloat162(h0, h1);
                dl[i] = __nv_bfloat162(__float2bfloat16(p0 - __bfloat162float(h0)),
                                       __float2bfloat16(p1 - __bfloat162float(h1)));
            }
            sum += __shfl_xor_sync(0xffffffffu, sum, 1);
            if (seg == 0) {
                smM[row] = mx;
                smL[row] = smL[row] * alpha + sum;
                smA[row] = alpha;
            }
        }
        __syncthreads();

        {
            const float a0 = smA[wid * 16 + r0];
            const float a1 = smA[wid * 16 + r0 + 8];
#pragma unroll
            for (int g = 0; g < 16; g++) {
                oa[g][0] *= a0; oa[g][1] *= a0;
                oa[g][2] *= a1; oa[g][3] *= a1;
            }
        }
#pragma unroll
        for (int kk = 0; kk < 4; kk++) {
            uint32_t pa = sb + FA_PH + (wid * 16 + lrow16) * VROWB + kk * 32 + lhalf;
            uint32_t ph[4], pl[4];
            ldsm_x4(pa,                   ph[0], ph[1], ph[2], ph[3]);
            ldsm_x4(pa + (FA_PL - FA_PH), pl[0], pl[1], pl[2], pl[3]);
#pragma unroll
            for (int g = 0; g < 8; g++) {
                uint32_t va = vbS + (g * 16 + lrow16) * VROWB + kk * 32 + lhalf;
                uint32_t vh0, vh1, vh2, vh3, vl0, vl1, vl2, vl3;
                ldsm_x4(va,         vh0, vh1, vh2, vh3);
                ldsm_x4(va + 18432, vl0, vl1, vl2, vl3);
                mma_bf16(oa[g * 2],     ph, vh0, vh2);
                mma_bf16(oa[g * 2 + 1], ph, vh1, vh3);
                mma_bf16(oa[g * 2],     ph, vl0, vl2);
                mma_bf16(oa[g * 2 + 1], ph, vl1, vl3);
                mma_bf16(oa[g * 2],     pl, vh0, vh2);
                mma_bf16(oa[g * 2 + 1], pl, vh1, vh3);
            }
        }
        __syncthreads();
        if (kt + 2 < NKT) issue(kt + 2);
    }

    const float inv0 = 1.0f / smL[wid * 16 + r0];
    const float inv1 = 1.0f / smL[wid * 16 + r0 + 8];
    const int row0 = qt * 128 + wid * 16 + r0;
#pragma unroll
    for (int g = 0; g < 16; g++) {
        const int col = (g >> 1) * 16 + (g & 1) * 8 + c2;
        const size_t i0 = (size_t)row0 * DIM + h * HD + col;
        const size_t i1 = (size_t)(row0 + 8) * DIM + h * HD + col;
        float v0 = oa[g][0] * inv0, v1 = oa[g][1] * inv0;
        float v2 = oa[g][2] * inv1, v3 = oa[g][3] * inv1;
        __nv_bfloat16 h0 = __float2bfloat16(v0), h1 = __float2bfloat16(v1);
        __nv_bfloat16 h2 = __float2bfloat16(v2), h3 = __float2bfloat16(v3);
        *(__nv_bfloat162*)(ohi + i0) = __nv_bfloat162(h0, h1);
        *(__nv_bfloat162*)(ohi + i1) = __nv_bfloat162(h2, h3);
        *(__nv_bfloat162*)(olo + i0) =
            __nv_bfloat162(__float2bfloat16(v0 - __bfloat162float(h0)),
                           __float2bfloat16(v1 - __bfloat162float(h1)));
        *(__nv_bfloat162*)(olo + i1) =
            __nv_bfloat162(__float2bfloat16(v2 - __bfloat162float(h2)),
                           __float2bfloat16(v3 - __bfloat162float(h3)));
    }
}

// ---------------- launch ---------------------------------------------------
template <typename T>
static T* symaddr(const void* sym)
{
    void* p = nullptr;
    cudaGetSymbolAddress(&p, sym);
    return (T*)p;
}

extern "C" void kernel_launch(void* const* d_in, const int* in_sizes, int n_in,
                              void* d_out, int out_size)
{
    const float* x       = (const float*)d_in[0];
    const float* wq      = (const float*)d_in[1];
    const float* bq      = (const float*)d_in[2];
    const float* wk      = (const float*)d_in[3];
    const float* bk      = (const float*)d_in[4];
    const float* wv      = (const float*)d_in[5];
    const float* bv      = (const float*)d_in[6];
    const float* wo      = (const float*)d_in[7];
    const float* bo      = (const float*)d_in[8];
    const float* lq_down = (const float*)d_in[9];
    const float* lq_up   = (const float*)d_in[10];
    const float* lk_down = (const float*)d_in[11];
    const float* lk_up   = (const float*)d_in[12];
    const float* lv_down = (const float*)d_in[13];
    const float* lv_up   = (const float*)d_in[14];
    const float* lo_down = (const float*)d_in[15];
    const float* lo_up   = (const float*)d_in[16];
    const float* nq_w    = (const float*)d_in[17];
    const float* nk_w    = (const float*)d_in[18];
    const float* fcos    = (const float*)d_in[19];
    const float* fsin    = (const float*)d_in[20];

    __nv_bfloat16* xhi = symaddr<__nv_bfloat16>(g_xhi);
    __nv_bfloat16* xlo = symaddr<__nv_bfloat16>(g_xlo);
    __nv_bfloat16* whi = symaddr<__nv_bfloat16>(g_whi);
    __nv_bfloat16* wlo = symaddr<__nv_bfloat16>(g_wlo);
    __nv_bfloat16* qhi = symaddr<__nv_bfloat16>(g_qhi);
    __nv_bfloat16* qlo = symaddr<__nv_bfloat16>(g_qlo);
    __nv_bfloat16* khi = symaddr<__nv_bfloat16>(g_khi);
    __nv_bfloat16* klo = symaddr<__nv_bfloat16>(g_klo);
    __nv_bfloat16* vthi = symaddr<__nv_bfloat16>(g_vthi);
    __nv_bfloat16* vtlo = symaddr<__nv_bfloat16>(g_vtlo);
    __nv_bfloat16* ohi = symaddr<__nv_bfloat16>(g_ohi);
    __nv_bfloat16* olo = symaddr<__nv_bfloat16>(g_olo);
    float* q = symaddr<float>(g_q);
    float* k = symaddr<float>(g_k);
    float* v = symaddr<float>(g_v);

    cudaFuncSetAttribute(gemm_hmma, cudaFuncAttributeMaxDynamicSharedMemorySize,
                         GEMM_SMEM);
    cudaFuncSetAttribute(flash_attn_tc, cudaFuncAttributeMaxDynamicSharedMemorySize,
                         FA_SMEM);

    const float scale = 16.0f / (float)RANK;   // ALPHA / R = 1.0
    const int   nel   = SEQ * DIM;
    const size_t WSZ  = (size_t)DIM * DIM;

    // 1) splits + effective weights
    split_bf16<<<(nel + 255) / 256, 256>>>(x, xhi, xlo, nel);
    PrepBatch pb;
    pb.w[0] = wq; pb.w[1] = wk; pb.w[2] = wv; pb.w[3] = wo;
    pb.ld[0] = lq_down; pb.ld[1] = lk_down; pb.ld[2] = lv_down; pb.ld[3] = lo_down;
    pb.lu[0] = lq_up;   pb.lu[1] = lk_up;   pb.lu[2] = lv_up;   pb.lu[3] = lo_up;
    for (int i = 0; i < 4; i++) { pb.hi[i] = whi + i * WSZ; pb.lo[i] = wlo + i * WSZ; }
    prep_weff_split<<<dim3(DIM / 256, DIM, 4), 256>>>(pb, scale);

    // 2) QKV projections: batched HMMA (bulk-async loads)
    GemmBatch gqkv;
    gqkv.bh[0] = whi + 0 * WSZ; gqkv.bh[1] = whi + 1 * WSZ; gqkv.bh[2] = whi + 2 * WSZ;
    gqkv.bl[0] = wlo + 0 * WSZ; gqkv.bl[1] = wlo + 1 * WSZ; gqkv.bl[2] = wlo + 2 * WSZ;
    gqkv.bias[0] = bq; gqkv.bias[1] = bk; gqkv.bias[2] = bv;
    gqkv.out[0] = q; gqkv.out[1] = k; gqkv.out[2] = v;
    gemm_hmma<<<dim3(DIM / 128, SEQ / 128, 3), 256, GEMM_SMEM>>>(xhi, xlo, gqkv);

    // 3) norm+rope -> bf16 splits; V transpose-split
    NormBatch nb;
    nb.X[0] = q; nb.X[1] = k;
    nb.w[0] = nq_w; nb.w[1] = nk_w;
    nb.hi[0] = qhi; nb.hi[1] = khi;
    nb.lo[0] = qlo; nb.lo[1] = klo;
    nb.outscale[0] = 0.08838834764831845f; nb.outscale[1] = 1.0f;
    rmsnorm_rope_split<<<dim3(SEQ, 2), 256>>>(nb, fcos, fsin);
    vtrans_split<<<dim3(SEQ / 32, HD / 32, NH), dim3(32, 8)>>>(v, vthi, vtlo);

    // 4) tensor-core flash attention (bulk-async loads)
    flash_attn_tc<<<dim3(SEQ / 128, NH), 256, FA_SMEM>>>(qhi, qlo, khi, klo,
                                                         vthi, vtlo, ohi, olo);

    // 5) output projection
    GemmBatch go;
    go.bh[0] = whi + 3 * WSZ; go.bh[1] = nullptr; go.bh[2] = nullptr;
    go.bl[0] = wlo + 3 * WSZ; go.bl[1] = nullptr; go.bl[2] = nullptr;
    go.bias[0] = bo; go.bias[1] = nullptr; go.bias[2] = nullptr;
    go.out[0] = (float*)d_out; go.out[1] = nullptr; go.out[2] = nullptr;
    gemm_hmma<<<dim3(DIM / 128, SEQ / 128, 1), 256, GEMM_SMEM>>>(ohi, olo, go);
}

// round 14
// speedup vs baseline: 1.1339x; 1.1339x over previous
#include <cuda_runtime.h>
#include <cuda_bf16.h>
#include <math.h>
#include <stdint.h>

#define DIM   2048
#define SEQ   3072
#define NH    16
#define HD    128
#define RANK  16
#define EPS_  1e-6f

// ---------------- scratch (static device memory; no allocs) ----------------
__device__ __nv_bfloat16 g_xhi[SEQ * DIM];
__device__ __nv_bfloat16 g_xlo[SEQ * DIM];
__device__ __nv_bfloat16 g_whi[4][DIM * DIM];
__device__ __nv_bfloat16 g_wlo[4][DIM * DIM];
__device__ __nv_bfloat16 g_qhi[SEQ * DIM];
__device__ __nv_bfloat16 g_qlo[SEQ * DIM];
__device__ __nv_bfloat16 g_khi[SEQ * DIM];
__device__ __nv_bfloat16 g_klo[SEQ * DIM];
__device__ __nv_bfloat16 g_vthi[NH * HD * SEQ];
__device__ __nv_bfloat16 g_vtlo[NH * HD * SEQ];
__device__ __nv_bfloat16 g_ohi[SEQ * DIM];
__device__ __nv_bfloat16 g_olo[SEQ * DIM];
__device__ float g_q[SEQ * DIM];
__device__ float g_k[SEQ * DIM];

// ---------------- PTX helpers ---------------------------------------------
__device__ __forceinline__ uint32_t smem_u32(const void* p)
{
    uint32_t a;
    asm("{ .reg .u64 t; cvta.to.shared.u64 t, %1; cvt.u32.u64 %0, t; }"
        : "=r"(a) : "l"(p));
    return a;
}

__device__ __forceinline__ void cp_async16(uint32_t s, const void* g)
{
    asm volatile("cp.async.cg.shared.global [%0], [%1], 16;" :: "r"(s), "l"(g));
}

__device__ __forceinline__ void cp_commit()
{
    asm volatile("cp.async.commit_group;" ::: "memory");
}

template <int N>
__device__ __forceinline__ void cp_wait()
{
    asm volatile("cp.async.wait_group %0;" :: "n"(N) : "memory");
}

__device__ __forceinline__ void ldsm_x4(uint32_t addr, uint32_t& r0, uint32_t& r1,
                                        uint32_t& r2, uint32_t& r3)
{
    asm volatile("ldmatrix.sync.aligned.m8n8.x4.shared.b16 {%0,%1,%2,%3}, [%4];"
                 : "=r"(r0), "=r"(r1), "=r"(r2), "=r"(r3) : "r"(addr));
}

__device__ __forceinline__ void mma_bf16(float* c,
                                         const uint32_t* a, uint32_t b0, uint32_t b1)
{
    asm volatile(
        "mma.sync.aligned.m16n8k16.row.col.f32.bf16.bf16.f32 "
        "{%0,%1,%2,%3}, {%4,%5,%6,%7}, {%8,%9}, {%0,%1,%2,%3};"
        : "+f"(c[0]), "+f"(c[1]), "+f"(c[2]), "+f"(c[3])
        : "r"(a[0]), "r"(a[1]), "r"(a[2]), "r"(a[3]), "r"(b0), "r"(b1));
}

// ---------------- batched param structs ------------------------------------
struct PrepBatch {
    const float* w[4];
    const float* ld[4];
    const float* lu[4];
    __nv_bfloat16* hi[4];
    __nv_bfloat16* lo[4];
};

struct GemmBatch {
    const __nv_bfloat16* bh[3];
    const __nv_bfloat16* bl[3];
    const float* bias[3];
    float* out[3];
    __nv_bfloat16* vh[3];   // non-null -> V-mode epilogue: write [h][d][s] hi/lo
    __nv_bfloat16* vl[3];
};

struct NormBatch {
    const float* X[2];
    const float* w[2];
    __nv_bfloat16* hi[2];
    __nv_bfloat16* lo[2];
    float outscale[2];
};

// ---------------- 1) effective weight prep + bf16 split (batched) ----------
__global__ __launch_bounds__(256) void prep_weff_split(PrepBatch P, float scale)
{
    const int z  = blockIdx.z;
    const int kx = blockIdx.x * 256 + threadIdx.x;
    const int j  = blockIdx.y;
    const float* lu = P.lu[z];
    const float* ld = P.ld[z];
    float acc = 0.f;
#pragma unroll
    for (int r = 0; r < RANK; r++)
        acc += lu[j * RANK + r] * ld[r * DIM + kx];
    float v = P.w[z][j * DIM + kx] + scale * acc;
    __nv_bfloat16 h = __float2bfloat16(v);
    P.hi[z][j * DIM + kx] = h;
    P.lo[z][j * DIM + kx] = __float2bfloat16(v - __bfloat162float(h));
}

// ---------------- 2) fp32 -> bf16 hi/lo split -------------------------------
__global__ __launch_bounds__(256) void split_bf16(const float* __restrict__ in,
                                                  __nv_bfloat16* __restrict__ hi,
                                                  __nv_bfloat16* __restrict__ lo,
                                                  int n)
{
    int i = blockIdx.x * 256 + threadIdx.x;
    if (i < n) {
        float v = in[i];
        __nv_bfloat16 h = __float2bfloat16(v);
        hi[i] = h;
        lo[i] = __float2bfloat16(v - __bfloat162float(h));
    }
}

// ---------------- 3) HMMA split-bf16 NT GEMM (R6 config: 128x128, 2-stage) --
#define KC        32
#define ROWB      80
#define TILEB     (128 * ROWB)             // 10240
#define STAGEB    (4 * TILEB)              // 40960
#define GEMM_SMEM (2 * STAGEB)             // 81920  -> 2 CTA/SM

__global__ __launch_bounds__(256) void gemm_hmma(const __nv_bfloat16* __restrict__ Ahi,
                                                 const __nv_bfloat16* __restrict__ Alo,
                                                 GemmBatch P)
{
    extern __shared__ __align__(128) char sm[];
    const uint32_t sbase = smem_u32(sm);

    const int tid  = threadIdx.x;
    const int wid  = tid >> 5;
    const int lane = tid & 31;
    const int zz = blockIdx.z;
    const int m0 = blockIdx.y * 128;
    const int n0 = blockIdx.x * 128;
    const int wm = wid & 3;
    const int wn = wid >> 2;

    const __nv_bfloat16* Bhi = P.bh[zz];
    const __nv_bfloat16* Blo = P.bl[zz];
    const float* bias = P.bias[zz];

    const int lrow = tid >> 1;
    const int lcp  = (tid & 1) * 2;
    const uint32_t srow = sbase + (uint32_t)lrow * ROWB + (uint32_t)lcp * 16;
    const __nv_bfloat16* gAh = Ahi + (size_t)(m0 + lrow) * DIM + lcp * 8;
    const __nv_bfloat16* gAl = Alo + (size_t)(m0 + lrow) * DIM + lcp * 8;
    const __nv_bfloat16* gBh = Bhi + (size_t)(n0 + lrow) * DIM + lcp * 8;
    const __nv_bfloat16* gBl = Blo + (size_t)(n0 + lrow) * DIM + lcp * 8;

    float acc[2][8][4];
#pragma unroll
    for (int i = 0; i < 2; i++)
#pragma unroll
        for (int j = 0; j < 8; j++)
#pragma unroll
            for (int e = 0; e < 4; e++) acc[i][j][e] = 0.f;

    const int NCH = DIM / KC;

    auto issue = [&](int c) {
        uint32_t b = srow + (uint32_t)(c & 1) * STAGEB;
        const int ko = c * KC;
        cp_async16(b + 0 * TILEB,      gAh + ko);
        cp_async16(b + 0 * TILEB + 16, gAh + ko + 8);
        cp_async16(b + 1 * TILEB,      gAl + ko);
        cp_async16(b + 1 * TILEB + 16, gAl + ko + 8);
        cp_async16(b + 2 * TILEB,      gBh + ko);
        cp_async16(b + 2 * TILEB + 16, gBh + ko + 8);
        cp_async16(b + 3 * TILEB,      gBl + ko);
        cp_async16(b + 3 * TILEB + 16, gBl + ko + 8);
        cp_commit();
    };

    issue(0);
    issue(1);

    const uint32_t lrow16 = (uint32_t)(lane & 15);
    const uint32_t lhalf  = (uint32_t)(lane >> 4) * 16;

    for (int c = 0; c < NCH; c++) {
        if (c == NCH - 1) cp_wait<0>(); else cp_wait<1>();
        __syncthreads();

        const uint32_t st = sbase + (uint32_t)(c & 1) * STAGEB;
        const uint32_t aRow = st + (uint32_t)(wm * 32) * ROWB;
        const uint32_t bRow = st + 2 * TILEB + (uint32_t)(wn * 64) * ROWB;

#pragma unroll
        for (int ks = 0; ks < 2; ks++) {
            const uint32_t kb = (uint32_t)(ks * 32) + lhalf;

            uint32_t ah[2][4], al[2][4];
#pragma unroll
            for (int im = 0; im < 2; im++) {
                uint32_t ra = aRow + (im * 16 + lrow16) * ROWB + kb;
                ldsm_x4(ra,         ah[im][0], ah[im][1], ah[im][2], ah[im][3]);
                ldsm_x4(ra + TILEB, al[im][0], al[im][1], al[im][2], al[im][3]);
            }

#pragma unroll
            for (int in4 = 0; in4 < 4; in4++) {
                uint32_t rb = bRow + (in4 * 16 + lrow16) * ROWB + kb;
                uint32_t bh0, bh1, bh2, bh3, bl0, bl1, bl2, bl3;
                ldsm_x4(rb,         bh0, bh1, bh2, bh3);
                ldsm_x4(rb + TILEB, bl0, bl1, bl2, bl3);

#pragma unroll
                for (int im = 0; im < 2; im++) {
                    float* c0 = acc[im][in4 * 2];
                    float* c1 = acc[im][in4 * 2 + 1];
                    mma_bf16(c0, ah[im], bh0, bh2);
                    mma_bf16(c1, ah[im], bh1, bh3);
                    mma_bf16(c0, ah[im], bl0, bl2);
                    mma_bf16(c1, ah[im], bl1, bl3);
                    mma_bf16(c0, al[im], bh0, bh2);
                    mma_bf16(c1, al[im], bh1, bh3);
                }
            }
        }
        __syncthreads();
        if (c + 2 < NCH) issue(c + 2);
    }

    const int r0 = lane >> 2;
    const int cpair = (lane & 3) * 2;

    if (P.vh[zz]) {
        // ---- V-mode epilogue: transpose through smem, write [h][d][s] ----
        // h = blockIdx.x (BN == HD == 128), d = col, s = m0 + row.
        float* T = (float*)sm;          // stride 132 floats; 128*132*4 = 67584 <= 81920
        __syncthreads();                // stages fully consumed; reuse smem
#pragma unroll
        for (int im = 0; im < 2; im++) {
#pragma unroll
            for (int jn = 0; jn < 8; jn++) {
                int col = wn * 64 + jn * 8 + cpair;
                int row = wm * 32 + im * 16 + r0;
                T[col * 132 + row]           = acc[im][jn][0];
                T[(col + 1) * 132 + row]     = acc[im][jn][1];
                T[col * 132 + row + 8]       = acc[im][jn][2];
                T[(col + 1) * 132 + row + 8] = acc[im][jn][3];
            }
        }
        __syncthreads();
        const int d  = tid >> 1;
        const int s0 = (tid & 1) * 64;
        const float bb = bias[n0 + d];
        const float* Tr = T + d * 132 + s0;
        __nv_bfloat16* vh = P.vh[zz] + (size_t)blockIdx.x * HD * SEQ
                          + (size_t)d * SEQ + m0 + s0;
        __nv_bfloat16* vl = P.vl[zz] + (size_t)blockIdx.x * HD * SEQ
                          + (size_t)d * SEQ + m0 + s0;
#pragma unroll
        for (int i = 0; i < 64; i += 2) {
            float v0 = Tr[i] + bb, v1 = Tr[i + 1] + bb;
            __nv_bfloat16 h0 = __float2bfloat16(v0);
            __nv_bfloat16 h1 = __float2bfloat16(v1);
            *(__nv_bfloat162*)(vh + i) = __nv_bfloat162(h0, h1);
            *(__nv_bfloat162*)(vl + i) =
                __nv_bfloat162(__float2bfloat16(v0 - __bfloat162float(h0)),
                               __float2bfloat16(v1 - __bfloat162float(h1)));
        }
    } else {
        float* C = P.out[zz];
#pragma unroll
        for (int im = 0; im < 2; im++) {
            const int mrow = m0 + wm * 32 + im * 16 + r0;
#pragma unroll
            for (int jn = 0; jn < 8; jn++) {
                const int col = n0 + wn * 64 + jn * 8 + cpair;
                const float b0 = bias[col], b1 = bias[col + 1];
                float* p0 = C + (size_t)mrow * DIM + col;
                float* p1 = C + (size_t)(mrow + 8) * DIM + col;
                *(float2*)p0 = make_float2(acc[im][jn][0] + b0, acc[im][jn][1] + b1);
                *(float2*)p1 = make_float2(acc[im][jn][2] + b0, acc[im][jn][3] + b1);
            }
        }
    }
}

// ---------------- 4) RMSNorm + RoPE + bf16 hi/lo split (batched q/k) -------
__global__ __launch_bounds__(256) void rmsnorm_rope_split(NormBatch P,
                                                          const float* __restrict__ fcos,
                                                          const float* __restrict__ fsin)
{
    const int z = blockIdx.y;
    const int s = blockIdx.x;
    const int tid = threadIdx.x;
    __shared__ float red[256];

    const float* row = P.X[z] + (size_t)s * DIM;
    const float* w = P.w[z];
    __nv_bfloat16* hi = P.hi[z];
    __nv_bfloat16* lo = P.lo[z];
    const float outscale = P.outscale[z];

    float ss = 0.f;
#pragma unroll
    for (int i = tid; i < DIM; i += 256) { float v = row[i]; ss += v * v; }
    red[tid] = ss;
    __syncthreads();
    for (int st = 128; st > 0; st >>= 1) {
        if (tid < st) red[tid] += red[tid + st];
        __syncthreads();
    }
    const float rs = rsqrtf(red[0] / (float)DIM + EPS_);

#pragma unroll
    for (int p = tid; p < DIM / 2; p += 256) {
        int hp = p & 63;
        float c  = fcos[s * HD + 2 * hp];
        float sn = fsin[s * HD + 2 * hp + 1];
        float x1 = row[2 * p]     * rs * w[2 * p];
        float x2 = row[2 * p + 1] * rs * w[2 * p + 1];
        float e = (x1 * c - x2 * sn) * outscale;
        float o = (x1 * sn + x2 * c) * outscale;
        __nv_bfloat16 eh = __float2bfloat16(e);
        __nv_bfloat16 oh = __float2bfloat16(o);
        hi[(size_t)s * DIM + 2 * p]     = eh;
        hi[(size_t)s * DIM + 2 * p + 1] = oh;
        lo[(size_t)s * DIM + 2 * p]     = __float2bfloat16(e - __bfloat162float(eh));
        lo[(size_t)s * DIM + 2 * p + 1] = __float2bfloat16(o - __bfloat162float(oh));
    }
}

// ---------------- 5) tensor-core flash attention (split-bf16) --------------
// CTA: 128 q-rows x 1 head, 256 threads = 8 warps, warp = 16 q-rows.
#define FA_KB   0
#define FA_VB   69632
#define FA_SS   143360
#define FA_PH   178176
#define FA_PL   196608
#define FA_MM   215040
#define FA_LL   215552
#define FA_AA   216064
#define FA_SMEM 216576
#define KROWB   272
#define VROWB   144
#define NKT     (SEQ / 64)

__global__ __launch_bounds__(256, 1) void flash_attn_tc(
    const __nv_bfloat16* __restrict__ qhi, const __nv_bfloat16* __restrict__ qlo,
    const __nv_bfloat16* __restrict__ khi, const __nv_bfloat16* __restrict__ klo,
    const __nv_bfloat16* __restrict__ vthi, const __nv_bfloat16* __restrict__ vtlo,
    __nv_bfloat16* __restrict__ ohi, __nv_bfloat16* __restrict__ olo)
{
    extern __shared__ __align__(128) char sm[];
    const uint32_t sb = smem_u32(sm);
    const int tid  = threadIdx.x;
    const int wid  = tid >> 5;
    const int lane = tid & 31;
    const int qt = blockIdx.x;
    const int h  = blockIdx.y;
    const uint32_t lrow16 = (uint32_t)(lane & 15);
    const uint32_t lhalf  = (uint32_t)(lane >> 4) * 16;
    const int r0 = lane >> 2;
    const int c2 = (lane & 3) * 2;

    float* smM = (float*)(sm + FA_MM);
    float* smL = (float*)(sm + FA_LL);
    float* smA = (float*)(sm + FA_AA);

    uint32_t qh[8][4], ql[8][4];
    const size_t qoff = (size_t)(qt * 128) * DIM + h * HD;
#pragma unroll
    for (int pass = 0; pass < 2; pass++) {
        const __nv_bfloat16* src = (pass == 0) ? (qhi + qoff) : (qlo + qoff);
        for (int c = tid; c < 2048; c += 256) {
            int row = c >> 4, o16 = c & 15;
            *(uint4*)(sm + FA_SS + row * KROWB + o16 * 16) =
                *(const uint4*)(src + (size_t)row * DIM + o16 * 8);
        }
        __syncthreads();
#pragma unroll
        for (int kk = 0; kk < 8; kk++) {
            uint32_t ra = sb + FA_SS + (wid * 16 + lrow16) * KROWB + kk * 32 + lhalf;
            if (pass == 0) ldsm_x4(ra, qh[kk][0], qh[kk][1], qh[kk][2], qh[kk][3]);
            else           ldsm_x4(ra, ql[kk][0], ql[kk][1], ql[kk][2], ql[kk][3]);
        }
        __syncthreads();
    }
    if (tid < 128) { smM[tid] = -1e30f; smL[tid] = 0.f; }

    float oa[16][4];
#pragma unroll
    for (int g = 0; g < 16; g++)
#pragma unroll
        for (int e = 0; e < 4; e++) oa[g][e] = 0.f;

    auto issue = [&](int kt) {
        const uint32_t stg = (uint32_t)(kt & 1);
        for (int i = 0; i < 4; i++) {
            int c = tid + i * 256;
            int row = c >> 4, o16 = c & 15;
            const size_t g = (size_t)(kt * 64 + row) * DIM + h * HD + o16 * 8;
            uint32_t d = sb + FA_KB + stg * 34816 + row * KROWB + o16 * 16;
            cp_async16(d,         khi + g);
            cp_async16(d + 17408, klo + g);
        }
        for (int i = 0; i < 4; i++) {
            int c = tid + i * 256;
            int row = c >> 3, o16 = c & 7;
            const size_t g = (size_t)h * HD * SEQ + (size_t)row * SEQ + kt * 64 + o16 * 8;
            uint32_t d = sb + FA_VB + stg * 36864 + row * VROWB + o16 * 16;
            cp_async16(d,         vthi + g);
            cp_async16(d + 18432, vtlo + g);
        }
        cp_commit();
    };

    issue(0);
    issue(1);

    for (int kt = 0; kt < NKT; kt++) {
        if (kt == NKT - 1) cp_wait<0>(); else cp_wait<1>();
        __syncthreads();
        const uint32_t kbS = sb + FA_KB + (uint32_t)(kt & 1) * 34816;
        const uint32_t vbS = sb + FA_VB + (uint32_t)(kt & 1) * 36864;

        float s[8][4];
#pragma unroll
        for (int g = 0; g < 8; g++)
#pragma unroll
            for (int e = 0; e < 4; e++) s[g][e] = 0.f;

#pragma unroll
        for (int kk = 0; kk < 8; kk++) {
#pragma unroll
            for (int j = 0; j < 4; j++) {
                uint32_t ra = kbS + (j * 16 + lrow16) * KROWB + kk * 32 + lhalf;
                uint32_t kh0, kh1, kh2, kh3, kl0, kl1, kl2, kl3;
                ldsm_x4(ra,         kh0, kh1, kh2, kh3);
                ldsm_x4(ra + 17408, kl0, kl1, kl2, kl3);
                mma_bf16(s[j * 2],     qh[kk], kh0, kh2);
                mma_bf16(s[j * 2 + 1], qh[kk], kh1, kh3);
                mma_bf16(s[j * 2],     qh[kk], kl0, kl2);
                mma_bf16(s[j * 2 + 1], qh[kk], kl1, kl3);
                mma_bf16(s[j * 2],     ql[kk], kh0, kh2);
                mma_bf16(s[j * 2 + 1], ql[kk], kh1, kh3);
            }
        }
#pragma unroll
        for (int g = 0; g < 8; g++) {
            int col = (g >> 1) * 16 + (g & 1) * 8 + c2;
            int row = wid * 16 + r0;
            *(float2*)(sm + FA_SS + row * KROWB + col * 4)       = make_float2(s[g][0], s[g][1]);
            *(float2*)(sm + FA_SS + (row + 8) * KROWB + col * 4) = make_float2(s[g][2], s[g][3]);
        }
        __syncthreads();

        {
            const int row = tid >> 1, seg = tid & 1;
            const float* sr = (const float*)(sm + FA_SS + row * KROWB + seg * 128);
            float v[32];
#pragma unroll
            for (int i = 0; i < 8; i++) {
                float4 f = *(const float4*)(sr + i * 4);
                v[i * 4] = f.x; v[i * 4 + 1] = f.y; v[i * 4 + 2] = f.z; v[i * 4 + 3] = f.w;
            }
            float mloc = v[0];
#pragma unroll
            for (int i = 1; i < 32; i++) mloc = fmaxf(mloc, v[i]);
            mloc = fmaxf(mloc, __shfl_xor_sync(0xffffffffu, mloc, 1));
            const float mold = smM[row];
            const float mx = fmaxf(mold, mloc);
            const float alpha = __expf(mold - mx);
            float sum = 0.f;
            __nv_bfloat162* dh = (__nv_bfloat162*)(sm + FA_PH + row * VROWB + seg * 64);
            __nv_bfloat162* dl = (__nv_bfloat162*)(sm + FA_PL + row * VROWB + seg * 64);
#pragma unroll
            for (int i = 0; i < 16; i++) {
                float p0 = __expf(v[2 * i]     - mx);
                float p1 = __expf(v[2 * i + 1] - mx);
                sum += p0 + p1;
                __nv_bfloat16 h0 = __float2bfloat16(p0);
                __nv_bfloat16 h1 = __float2bfloat16(p1);
                dh[i] = __nv_bfloat162(h0, h1);
                dl[i] = __nv_bfloat162(__float2bfloat16(p0 - __bfloat162float(h0)),
                                       __float2bfloat16(p1 - __bfloat162float(h1)));
            }
            sum += __shfl_xor_sync(0xffffffffu, sum, 1);
            if (seg == 0) {
                smM[row] = mx;
                smL[row] = smL[row] * alpha + sum;
                smA[row] = alpha;
            }
        }
        __syncthreads();

        {
            const float a0 = smA[wid * 16 + r0];
            const float a1 = smA[wid * 16 + r0 + 8];
#pragma unroll
            for (int g = 0; g < 16; g++) {
                oa[g][0] *= a0; oa[g][1] *= a0;
                oa[g][2] *= a1; oa[g][3] *= a1;
            }
        }
#pragma unroll
        for (int kk = 0; kk < 4; kk++) {
            uint32_t pa = sb + FA_PH + (wid * 16 + lrow16) * VROWB + kk * 32 + lhalf;
            uint32_t ph[4], pl[4];
            ldsm_x4(pa,                   ph[0], ph[1], ph[2], ph[3]);
            ldsm_x4(pa + (FA_PL - FA_PH), pl[0], pl[1], pl[2], pl[3]);
#pragma unroll
            for (int g = 0; g < 8; g++) {
                uint32_t va = vbS + (g * 16 + lrow16) * VROWB + kk * 32 + lhalf;
                uint32_t vh0, vh1, vh2, vh3, vl0, vl1, vl2, vl3;
                ldsm_x4(va,         vh0, vh1, vh2, vh3);
                ldsm_x4(va + 18432, vl0, vl1, vl2, vl3);
                mma_bf16(oa[g * 2],     ph, vh0, vh2);
                mma_bf16(oa[g * 2 + 1], ph, vh1, vh3);
                mma_bf16(oa[g * 2],     ph, vl0, vl2);
                mma_bf16(oa[g * 2 + 1], ph, vl1, vl3);
                mma_bf16(oa[g * 2],     pl, vh0, vh2);
                mma_bf16(oa[g * 2 + 1], pl, vh1, vh3);
            }
        }
        __syncthreads();
        if (kt + 2 < NKT) issue(kt + 2);
    }

    const float inv0 = 1.0f / smL[wid * 16 + r0];
    const float inv1 = 1.0f / smL[wid * 16 + r0 + 8];
    const int row0 = qt * 128 + wid * 16 + r0;
#pragma unroll
    for (int g = 0; g < 16; g++) {
        const int col = (g >> 1) * 16 + (g & 1) * 8 + c2;
        const size_t i0 = (size_t)row0 * DIM + h * HD + col;
        const size_t i1 = (size_t)(row0 + 8) * DIM + h * HD + col;
        float v0 = oa[g][0] * inv0, v1 = oa[g][1] * inv0;
        float v2 = oa[g][2] * inv1, v3 = oa[g][3] * inv1;
        __nv_bfloat16 h0 = __float2bfloat16(v0), h1 = __float2bfloat16(v1);
        __nv_bfloat16 h2 = __float2bfloat16(v2), h3 = __float2bfloat16(v3);
        *(__nv_bfloat162*)(ohi + i0) = __nv_bfloat162(h0, h1);
        *(__nv_bfloat162*)(ohi + i1) = __nv_bfloat162(h2, h3);
        *(__nv_bfloat162*)(olo + i0) =
            __nv_bfloat162(__float2bfloat16(v0 - __bfloat162float(h0)),
                           __float2bfloat16(v1 - __bfloat162float(h1)));
        *(__nv_bfloat162*)(olo + i1) =
            __nv_bfloat162(__float2bfloat16(v2 - __bfloat162float(h2)),
                           __float2bfloat16(v3 - __bfloat162float(h3)));
    }
}

// ---------------- launch ---------------------------------------------------
template <typename T>
static T* symaddr(const void* sym)
{
    void* p = nullptr;
    cudaGetSymbolAddress(&p, sym);
    return (T*)p;
}

extern "C" void kernel_launch(void* const* d_in, const int* in_sizes, int n_in,
                              void* d_out, int out_size)
{
    const float* x       = (const float*)d_in[0];
    const float* wq      = (const float*)d_in[1];
    const float* bq      = (const float*)d_in[2];
    const float* wk      = (const float*)d_in[3];
    const float* bk      = (const float*)d_in[4];
    const float* wv      = (const float*)d_in[5];
    const float* bv      = (const float*)d_in[6];
    const float* wo      = (const float*)d_in[7];
    const float* bo      = (const float*)d_in[8];
    const float* lq_down = (const float*)d_in[9];
    const float* lq_up   = (const float*)d_in[10];
    const float* lk_down = (const float*)d_in[11];
    const float* lk_up   = (const float*)d_in[12];
    const float* lv_down = (const float*)d_in[13];
    const float* lv_up   = (const float*)d_in[14];
    const float* lo_down = (const float*)d_in[15];
    const float* lo_up   = (const float*)d_in[16];
    const float* nq_w    = (const float*)d_in[17];
    const float* nk_w    = (const float*)d_in[18];
    const float* fcos    = (const float*)d_in[19];
    const float* fsin    = (const float*)d_in[20];

    __nv_bfloat16* xhi = symaddr<__nv_bfloat16>(g_xhi);
    __nv_bfloat16* xlo = symaddr<__nv_bfloat16>(g_xlo);
    __nv_bfloat16* whi = symaddr<__nv_bfloat16>(g_whi);
    __nv_bfloat16* wlo = symaddr<__nv_bfloat16>(g_wlo);
    __nv_bfloat16* qhi = symaddr<__nv_bfloat16>(g_qhi);
    __nv_bfloat16* qlo = symaddr<__nv_bfloat16>(g_qlo);
    __nv_bfloat16* khi = symaddr<__nv_bfloat16>(g_khi);
    __nv_bfloat16* klo = symaddr<__nv_bfloat16>(g_klo);
    __nv_bfloat16* vthi = symaddr<__nv_bfloat16>(g_vthi);
    __nv_bfloat16* vtlo = symaddr<__nv_bfloat16>(g_vtlo);
    __nv_bfloat16* ohi = symaddr<__nv_bfloat16>(g_ohi);
    __nv_bfloat16* olo = symaddr<__nv_bfloat16>(g_olo);
    float* q = symaddr<float>(g_q);
    float* k = symaddr<float>(g_k);

    cudaFuncSetAttribute(gemm_hmma, cudaFuncAttributeMaxDynamicSharedMemorySize,
                         GEMM_SMEM);
    cudaFuncSetAttribute(flash_attn_tc, cudaFuncAttributeMaxDynamicSharedMemorySize,
                         FA_SMEM);

    const float scale = 16.0f / (float)RANK;   // ALPHA / R = 1.0
    const int   nel   = SEQ * DIM;
    const size_t WSZ  = (size_t)DIM * DIM;

    // 1) splits + effective weights
    split_bf16<<<(nel + 255) / 256, 256>>>(x, xhi, xlo, nel);
    PrepBatch pb;
    pb.w[0] = wq; pb.w[1] = wk; pb.w[2] = wv; pb.w[3] = wo;
    pb.ld[0] = lq_down; pb.ld[1] = lk_down; pb.ld[2] = lv_down; pb.ld[3] = lo_down;
    pb.lu[0] = lq_up;   pb.lu[1] = lk_up;   pb.lu[2] = lv_up;   pb.lu[3] = lo_up;
    for (int i = 0; i < 4; i++) { pb.hi[i] = whi + i * WSZ; pb.lo[i] = wlo + i * WSZ; }
    prep_weff_split<<<dim3(DIM / 256, DIM, 4), 256>>>(pb, scale);

    // 2) QKV projections: batched HMMA; V writes transposed hi/lo directly
    GemmBatch gqkv;
    gqkv.bh[0] = whi + 0 * WSZ; gqkv.bh[1] = whi + 1 * WSZ; gqkv.bh[2] = whi + 2 * WSZ;
    gqkv.bl[0] = wlo + 0 * WSZ; gqkv.bl[1] = wlo + 1 * WSZ; gqkv.bl[2] = wlo + 2 * WSZ;
    gqkv.bias[0] = bq; gqkv.bias[1] = bk; gqkv.bias[2] = bv;
    gqkv.out[0] = q; gqkv.out[1] = k; gqkv.out[2] = nullptr;
    gqkv.vh[0] = nullptr; gqkv.vh[1] = nullptr; gqkv.vh[2] = vthi;
    gqkv.vl[0] = nullptr; gqkv.vl[1] = nullptr; gqkv.vl[2] = vtlo;
    gemm_hmma<<<dim3(DIM / 128, SEQ / 128, 3), 256, GEMM_SMEM>>>(xhi, xlo, gqkv);

    // 3) norm+rope -> bf16 splits (V already done in GEMM epilogue)
    NormBatch nb;
    nb.X[0] = q; nb.X[1] = k;
    nb.w[0] = nq_w; nb.w[1] = nk_w;
    nb.hi[0] = qhi; nb.hi[1] = khi;
    nb.lo[0] = qlo; nb.lo[1] = klo;
    nb.outscale[0] = 0.08838834764831845f; nb.outscale[1] = 1.0f;
    rmsnorm_rope_split<<<dim3(SEQ, 2), 256>>>(nb, fcos, fsin);

    // 4) tensor-core flash attention (128-row q tiles)
    flash_attn_tc<<<dim3(SEQ / 128, NH), 256, FA_SMEM>>>(qhi, qlo, khi, klo,
                                                         vthi, vtlo, ohi, olo);

    // 5) output projection (HMMA)
    GemmBatch go;
    go.bh[0] = whi + 3 * WSZ; go.bh[1] = nullptr; go.bh[2] = nullptr;
    go.bl[0] = wlo + 3 * WSZ; go.bl[1] = nullptr; go.bl[2] = nullptr;
    go.bias[0] = bo; go.bias[1] = nullptr; go.bias[2] = nullptr;
    go.out[0] = (float*)d_out; go.out[1] = nullptr; go.out[2] = nullptr;
    go.vh[0] = nullptr; go.vh[1] = nullptr; go.vh[2] = nullptr;
    go.vl[0] = nullptr; go.vl[1] = nullptr; go.vl[2] = nullptr;
    gemm_hmma<<<dim3(DIM / 128, SEQ / 128, 1), 256, GEMM_SMEM>>>(ohi, olo, go);
}

// round 16
// speedup vs baseline: 1.1914x; 1.0508x over previous
#include <cuda_runtime.h>
#include <cuda_bf16.h>
#include <cuda_fp16.h>
#include <math.h>
#include <stdint.h>

#define DIM   2048
#define SEQ   3072
#define NH    16
#define HD    128
#define RANK  16
#define EPS_  1e-6f

// ---------------- scratch (static device memory; no allocs) ----------------
__device__ __half g_xu[SEQ * DIM];
__device__ __half g_xw[SEQ * DIM];
__device__ __half g_wu[4][DIM * DIM];
__device__ __half g_ww[4][DIM * DIM];
__device__ __half g_ou[SEQ * DIM];
__device__ __half g_ow[SEQ * DIM];
__device__ __nv_bfloat16 g_qhi[SEQ * DIM];
__device__ __nv_bfloat16 g_qlo[SEQ * DIM];
__device__ __nv_bfloat16 g_khi[SEQ * DIM];
__device__ __nv_bfloat16 g_klo[SEQ * DIM];
__device__ __nv_bfloat16 g_vthi[NH * HD * SEQ];
__device__ __nv_bfloat16 g_vtlo[NH * HD * SEQ];
__device__ float g_q[SEQ * DIM];
__device__ float g_k[SEQ * DIM];
__device__ float g_v[SEQ * DIM];

// ---------------- PTX helpers ---------------------------------------------
__device__ __forceinline__ uint32_t smem_u32(const void* p)
{
    uint32_t a;
    asm("{ .reg .u64 t; cvta.to.shared.u64 t, %1; cvt.u32.u64 %0, t; }"
        : "=r"(a) : "l"(p));
    return a;
}

__device__ __forceinline__ void cp_async16(uint32_t s, const void* g)
{
    asm volatile("cp.async.cg.shared.global [%0], [%1], 16;" :: "r"(s), "l"(g));
}

__device__ __forceinline__ void cp_commit()
{
    asm volatile("cp.async.commit_group;" ::: "memory");
}

template <int N>
__device__ __forceinline__ void cp_wait()
{
    asm volatile("cp.async.wait_group %0;" :: "n"(N) : "memory");
}

__device__ __forceinline__ void ldsm_x4(uint32_t addr, uint32_t& r0, uint32_t& r1,
                                        uint32_t& r2, uint32_t& r3)
{
    asm volatile("ldmatrix.sync.aligned.m8n8.x4.shared.b16 {%0,%1,%2,%3}, [%4];"
                 : "=r"(r0), "=r"(r1), "=r"(r2), "=r"(r3) : "r"(addr));
}

__device__ __forceinline__ void mma_bf16(float* c,
                                         const uint32_t* a, uint32_t b0, uint32_t b1)
{
    asm volatile(
        "mma.sync.aligned.m16n8k16.row.col.f32.bf16.bf16.f32 "
        "{%0,%1,%2,%3}, {%4,%5,%6,%7}, {%8,%9}, {%0,%1,%2,%3};"
        : "+f"(c[0]), "+f"(c[1]), "+f"(c[2]), "+f"(c[3])
        : "r"(a[0]), "r"(a[1]), "r"(a[2]), "r"(a[3]), "r"(b0), "r"(b1));
}

__device__ __forceinline__ void mma_fp16(float* c,
                                         const uint32_t* a, uint32_t b0, uint32_t b1)
{
    asm volatile(
        "mma.sync.aligned.m16n8k16.row.col.f32.f16.f16.f32 "
        "{%0,%1,%2,%3}, {%4,%5,%6,%7}, {%8,%9}, {%0,%1,%2,%3};"
        : "+f"(c[0]), "+f"(c[1]), "+f"(c[2]), "+f"(c[3])
        : "r"(a[0]), "r"(a[1]), "r"(a[2]), "r"(a[3]), "r"(b0), "r"(b1));
}

// u = fp16(v); w = fp16(u + 32*(v-u)) = fp16(32v - 31u)
__device__ __forceinline__ void uw_split(float v, __half& u, __half& w)
{
    u = __float2half_rn(v);
    float uf = __half2float(u);
    w = __float2half_rn(fmaf(32.f, v, -31.f * uf));
}

// ---------------- batched param structs ------------------------------------
struct PrepBatch {
    const float* w[4];
    const float* ld[4];
    const float* lu[4];
    __half* U[4];
    __half* W[4];
};

struct GemmBatch {
    const __half* bu[3];
    const __half* bw[3];
    const float* bias[3];
    float* out[3];
};

struct NormBatch {
    const float* X[2];
    const float* w[2];
    __nv_bfloat16* hi[2];
    __nv_bfloat16* lo[2];
    float outscale[2];
};

// ---------------- 1) effective weight prep + fp16 U/W split ----------------
__global__ __launch_bounds__(256) void prep_weff_split(PrepBatch P, float scale)
{
    const int z  = blockIdx.z;
    const int kx = blockIdx.x * 256 + threadIdx.x;
    const int j  = blockIdx.y;
    const float* lu = P.lu[z];
    const float* ld = P.ld[z];
    float acc = 0.f;
#pragma unroll
    for (int r = 0; r < RANK; r++)
        acc += lu[j * RANK + r] * ld[r * DIM + kx];
    float v = P.w[z][j * DIM + kx] + scale * acc;
    __half u, w;
    uw_split(v, u, w);
    P.U[z][j * DIM + kx] = u;
    P.W[z][j * DIM + kx] = w;
}

// ---------------- 2) fp32 -> fp16 U/W split ---------------------------------
__global__ __launch_bounds__(256) void split_uw(const float* __restrict__ in,
                                                __half* __restrict__ U,
                                                __half* __restrict__ W,
                                                int n)
{
    int i = blockIdx.x * 256 + threadIdx.x;
    if (i < n) {
        __half u, w;
        uw_split(in[i], u, w);
        U[i] = u;
        W[i] = w;
    }
}

// ---------------- 3) fp16 2-MMA emulated-fp32 NT GEMM (128x128, 2-stage) ----
// C = sum U_A U_B, D = sum W_A W_B; out = C + (D - C)/32 + bias.
#define KC        32
#define ROWB      80
#define TILEB     (128 * ROWB)             // 10240
#define STAGEB    (4 * TILEB)              // 40960
#define GEMM_SMEM (2 * STAGEB)             // 81920 -> 2 CTA/SM

__global__ __launch_bounds__(256) void gemm_hmma(const __half* __restrict__ Au,
                                                 const __half* __restrict__ Aw,
                                                 GemmBatch P)
{
    extern __shared__ __align__(128) char sm[];
    const uint32_t sbase = smem_u32(sm);

    const int tid  = threadIdx.x;
    const int wid  = tid >> 5;
    const int lane = tid & 31;
    const int zz = blockIdx.z;
    const int m0 = blockIdx.y * 128;
    const int n0 = blockIdx.x * 128;
    const int wm = wid & 3;
    const int wn = wid >> 2;

    const __half* Bu = P.bu[zz];
    const __half* Bw = P.bw[zz];
    const float* bias = P.bias[zz];
    float* C = P.out[zz];

    const int lrow = tid >> 1;
    const int lcp  = (tid & 1) * 2;
    const uint32_t srow = sbase + (uint32_t)lrow * ROWB + (uint32_t)lcp * 16;
    const __half* gAu = Au + (size_t)(m0 + lrow) * DIM + lcp * 8;
    const __half* gAw = Aw + (size_t)(m0 + lrow) * DIM + lcp * 8;
    const __half* gBu = Bu + (size_t)(n0 + lrow) * DIM + lcp * 8;
    const __half* gBw = Bw + (size_t)(n0 + lrow) * DIM + lcp * 8;

    float accC[2][8][4], accD[2][8][4];
#pragma unroll
    for (int i = 0; i < 2; i++)
#pragma unroll
        for (int j = 0; j < 8; j++)
#pragma unroll
            for (int e = 0; e < 4; e++) { accC[i][j][e] = 0.f; accD[i][j][e] = 0.f; }

    const int NCH = DIM / KC;

    auto issue = [&](int c) {
        uint32_t b = srow + (uint32_t)(c & 1) * STAGEB;
        const int ko = c * KC;
        cp_async16(b + 0 * TILEB,      gAu + ko);
        cp_async16(b + 0 * TILEB + 16, gAu + ko + 8);
        cp_async16(b + 1 * TILEB,      gAw + ko);
        cp_async16(b + 1 * TILEB + 16, gAw + ko + 8);
        cp_async16(b + 2 * TILEB,      gBu + ko);
        cp_async16(b + 2 * TILEB + 16, gBu + ko + 8);
        cp_async16(b + 3 * TILEB,      gBw + ko);
        cp_async16(b + 3 * TILEB + 16, gBw + ko + 8);
        cp_commit();
    };

    issue(0);
    issue(1);

    const uint32_t lrow16 = (uint32_t)(lane & 15);
    const uint32_t lhalf  = (uint32_t)(lane >> 4) * 16;

    for (int c = 0; c < NCH; c++) {
        if (c == NCH - 1) cp_wait<0>(); else cp_wait<1>();
        __syncthreads();

        const uint32_t st = sbase + (uint32_t)(c & 1) * STAGEB;
        const uint32_t aRow = st + (uint32_t)(wm * 32) * ROWB;
        const uint32_t bRow = st + 2 * TILEB + (uint32_t)(wn * 64) * ROWB;

#pragma unroll
        for (int ks = 0; ks < 2; ks++) {
            const uint32_t kb = (uint32_t)(ks * 32) + lhalf;

            uint32_t uA[2][4], wA[2][4];
#pragma unroll
            for (int im = 0; im < 2; im++) {
                uint32_t ra = aRow + (im * 16 + lrow16) * ROWB + kb;
                ldsm_x4(ra,         uA[im][0], uA[im][1], uA[im][2], uA[im][3]);
                ldsm_x4(ra + TILEB, wA[im][0], wA[im][1], wA[im][2], wA[im][3]);
            }

#pragma unroll
            for (int in4 = 0; in4 < 4; in4++) {
                uint32_t rb = bRow + (in4 * 16 + lrow16) * ROWB + kb;
                uint32_t bu0, bu1, bu2, bu3, bw0, bw1, bw2, bw3;
                ldsm_x4(rb,         bu0, bu1, bu2, bu3);
                ldsm_x4(rb + TILEB, bw0, bw1, bw2, bw3);

#pragma unroll
                for (int im = 0; im < 2; im++) {
                    mma_fp16(accC[im][in4 * 2],     uA[im], bu0, bu2);
                    mma_fp16(accC[im][in4 * 2 + 1], uA[im], bu1, bu3);
                    mma_fp16(accD[im][in4 * 2],     wA[im], bw0, bw2);
                    mma_fp16(accD[im][in4 * 2 + 1], wA[im], bw1, bw3);
                }
            }
        }
        __syncthreads();
        if (c + 2 < NCH) issue(c + 2);
    }

    const int r0 = lane >> 2;
    const int cpair = (lane & 3) * 2;
#pragma unroll
    for (int im = 0; im < 2; im++) {
        const int mrow = m0 + wm * 32 + im * 16 + r0;
#pragma unroll
        for (int jn = 0; jn < 8; jn++) {
            const int col = n0 + wn * 64 + jn * 8 + cpair;
            const float b0 = bias[col], b1 = bias[col + 1];
            float* cc = accC[im][jn];
            float* dd = accD[im][jn];
            float v0 = cc[0] + (dd[0] - cc[0]) * 0.03125f + b0;
            float v1 = cc[1] + (dd[1] - cc[1]) * 0.03125f + b1;
            float v2 = cc[2] + (dd[2] - cc[2]) * 0.03125f + b0;
            float v3 = cc[3] + (dd[3] - cc[3]) * 0.03125f + b1;
            float* p0 = C + (size_t)mrow * DIM + col;
            float* p1 = C + (size_t)(mrow + 8) * DIM + col;
            *(float2*)p0 = make_float2(v0, v1);
            *(float2*)p1 = make_float2(v2, v3);
        }
    }
}

// ---------------- 4) RMSNorm + RoPE + bf16 hi/lo split (batched q/k) -------
__global__ __launch_bounds__(256) void rmsnorm_rope_split(NormBatch P,
                                                          const float* __restrict__ fcos,
                                                          const float* __restrict__ fsin)
{
    const int z = blockIdx.y;
    const int s = blockIdx.x;
    const int tid = threadIdx.x;
    __shared__ float red[256];

    const float* row = P.X[z] + (size_t)s * DIM;
    const float* w = P.w[z];
    __nv_bfloat16* hi = P.hi[z];
    __nv_bfloat16* lo = P.lo[z];
    const float outscale = P.outscale[z];

    float ss = 0.f;
#pragma unroll
    for (int i = tid; i < DIM; i += 256) { float v = row[i]; ss += v * v; }
    red[tid] = ss;
    __syncthreads();
    for (int st = 128; st > 0; st >>= 1) {
        if (tid < st) red[tid] += red[tid + st];
        __syncthreads();
    }
    const float rs = rsqrtf(red[0] / (float)DIM + EPS_);

#pragma unroll
    for (int p = tid; p < DIM / 2; p += 256) {
        int hp = p & 63;
        float c  = fcos[s * HD + 2 * hp];
        float sn = fsin[s * HD + 2 * hp + 1];
        float x1 = row[2 * p]     * rs * w[2 * p];
        float x2 = row[2 * p + 1] * rs * w[2 * p + 1];
        float e = (x1 * c - x2 * sn) * outscale;
        float o = (x1 * sn + x2 * c) * outscale;
        __nv_bfloat16 eh = __float2bfloat16(e);
        __nv_bfloat16 oh = __float2bfloat16(o);
        hi[(size_t)s * DIM + 2 * p]     = eh;
        hi[(size_t)s * DIM + 2 * p + 1] = oh;
        lo[(size_t)s * DIM + 2 * p]     = __float2bfloat16(e - __bfloat162float(eh));
        lo[(size_t)s * DIM + 2 * p + 1] = __float2bfloat16(o - __bfloat162float(oh));
    }
}

// ---------------- 5) V transpose + split: [s][h*128+d] -> [h][d][s] --------
__global__ __launch_bounds__(256) void vtrans_split(const float* __restrict__ V,
                                                    __nv_bfloat16* __restrict__ vthi,
                                                    __nv_bfloat16* __restrict__ vtlo)
{
    __shared__ float t[32][33];
    const int s0 = blockIdx.x * 32;
    const int d0 = blockIdx.y * 32;
    const int h  = blockIdx.z;
    const int tx = threadIdx.x;
    const int ty = threadIdx.y;

    for (int i = ty; i < 32; i += 8)
        t[i][tx] = V[(size_t)(s0 + i) * DIM + h * HD + d0 + tx];
    __syncthreads();
    for (int i = ty; i < 32; i += 8) {
        float v = t[tx][i];
        __nv_bfloat16 hv = __float2bfloat16(v);
        size_t idx = (size_t)h * HD * SEQ + (size_t)(d0 + i) * SEQ + s0 + tx;
        vthi[idx] = hv;
        vtlo[idx] = __float2bfloat16(v - __bfloat162float(hv));
    }
}

// ---------------- 6) tensor-core flash attention (split-bf16) --------------
// CTA: 128 q-rows x 1 head, 256 threads = 8 warps, warp = 16 q-rows.
#define FA_KB   0
#define FA_VB   69632
#define FA_SS   143360
#define FA_PH   178176
#define FA_PL   196608
#define FA_MM   215040
#define FA_LL   215552
#define FA_AA   216064
#define FA_SMEM 216576
#define KROWB   272
#define VROWB   144
#define NKT     (SEQ / 64)

__global__ __launch_bounds__(256, 1) void flash_attn_tc(
    const __nv_bfloat16* __restrict__ qhi, const __nv_bfloat16* __restrict__ qlo,
    const __nv_bfloat16* __restrict__ khi, const __nv_bfloat16* __restrict__ klo,
    const __nv_bfloat16* __restrict__ vthi, const __nv_bfloat16* __restrict__ vtlo,
    __half* __restrict__ ou, __half* __restrict__ ow)
{
    extern __shared__ __align__(128) char sm[];
    const uint32_t sb = smem_u32(sm);
    const int tid  = threadIdx.x;
    const int wid  = tid >> 5;
    const int lane = tid & 31;
    const int qt = blockIdx.x;
    const int h  = blockIdx.y;
    const uint32_t lrow16 = (uint32_t)(lane & 15);
    const uint32_t lhalf  = (uint32_t)(lane >> 4) * 16;
    const int r0 = lane >> 2;
    const int c2 = (lane & 3) * 2;

    float* smM = (float*)(sm + FA_MM);
    float* smL = (float*)(sm + FA_LL);
    float* smA = (float*)(sm + FA_AA);

    uint32_t qh[8][4], ql[8][4];
    const size_t qoff = (size_t)(qt * 128) * DIM + h * HD;
#pragma unroll
    for (int pass = 0; pass < 2; pass++) {
        const __nv_bfloat16* src = (pass == 0) ? (qhi + qoff) : (qlo + qoff);
        for (int c = tid; c < 2048; c += 256) {
            int row = c >> 4, o16 = c & 15;
            *(uint4*)(sm + FA_SS + row * KROWB + o16 * 16) =
                *(const uint4*)(src + (size_t)row * DIM + o16 * 8);
        }
        __syncthreads();
#pragma unroll
        for (int kk = 0; kk < 8; kk++) {
            uint32_t ra = sb + FA_SS + (wid * 16 + lrow16) * KROWB + kk * 32 + lhalf;
            if (pass == 0) ldsm_x4(ra, qh[kk][0], qh[kk][1], qh[kk][2], qh[kk][3]);
            else           ldsm_x4(ra, ql[kk][0], ql[kk][1], ql[kk][2], ql[kk][3]);
        }
        __syncthreads();
    }
    if (tid < 128) { smM[tid] = -1e30f; smL[tid] = 0.f; }

    float oa[16][4];
#pragma unroll
    for (int g = 0; g < 16; g++)
#pragma unroll
        for (int e = 0; e < 4; e++) oa[g][e] = 0.f;

    auto issue = [&](int kt) {
        const uint32_t stg = (uint32_t)(kt & 1);
        for (int i = 0; i < 4; i++) {
            int c = tid + i * 256;
            int row = c >> 4, o16 = c & 15;
            const size_t g = (size_t)(kt * 64 + row) * DIM + h * HD + o16 * 8;
            uint32_t d = sb + FA_KB + stg * 34816 + row * KROWB + o16 * 16;
            cp_async16(d,         khi + g);
            cp_async16(d + 17408, klo + g);
        }
        for (int i = 0; i < 4; i++) {
            int c = tid + i * 256;
            int row = c >> 3, o16 = c & 7;
            const size_t g = (size_t)h * HD * SEQ + (size_t)row * SEQ + kt * 64 + o16 * 8;
            uint32_t d = sb + FA_VB + stg * 36864 + row * VROWB + o16 * 16;
            cp_async16(d,         vthi + g);
            cp_async16(d + 18432, vtlo + g);
        }
        cp_commit();
    };

    issue(0);
    issue(1);

    for (int kt = 0; kt < NKT; kt++) {
        if (kt == NKT - 1) cp_wait<0>(); else cp_wait<1>();
        __syncthreads();
        const uint32_t kbS = sb + FA_KB + (uint32_t)(kt & 1) * 34816;
        const uint32_t vbS = sb + FA_VB + (uint32_t)(kt & 1) * 36864;

        float s[8][4];
#pragma unroll
        for (int g = 0; g < 8; g++)
#pragma unroll
            for (int e = 0; e < 4; e++) s[g][e] = 0.f;

#pragma unroll
        for (int kk = 0; kk < 8; kk++) {
#pragma unroll
            for (int j = 0; j < 4; j++) {
                uint32_t ra = kbS + (j * 16 + lrow16) * KROWB + kk * 32 + lhalf;
                uint32_t kh0, kh1, kh2, kh3, kl0, kl1, kl2, kl3;
                ldsm_x4(ra,         kh0, kh1, kh2, kh3);
                ldsm_x4(ra + 17408, kl0, kl1, kl2, kl3);
                mma_bf16(s[j * 2],     qh[kk], kh0, kh2);
                mma_bf16(s[j * 2 + 1], qh[kk], kh1, kh3);
                mma_bf16(s[j * 2],     qh[kk], kl0, kl2);
                mma_bf16(s[j * 2 + 1], qh[kk], kl1, kl3);
                mma_bf16(s[j * 2],     ql[kk], kh0, kh2);
                mma_bf16(s[j * 2 + 1], ql[kk], kh1, kh3);
            }
        }
#pragma unroll
        for (int g = 0; g < 8; g++) {
            int col = (g >> 1) * 16 + (g & 1) * 8 + c2;
            int row = wid * 16 + r0;
            *(float2*)(sm + FA_SS + row * KROWB + col * 4)       = make_float2(s[g][0], s[g][1]);
            *(float2*)(sm + FA_SS + (row + 8) * KROWB + col * 4) = make_float2(s[g][2], s[g][3]);
        }
        __syncthreads();

        {
            const int row = tid >> 1, seg = tid & 1;
            const float* sr = (const float*)(sm + FA_SS + row * KROWB + seg * 128);
            float v[32];
#pragma unroll
            for (int i = 0; i < 8; i++) {
                float4 f = *(const float4*)(sr + i * 4);
                v[i * 4] = f.x; v[i * 4 + 1] = f.y; v[i * 4 + 2] = f.z; v[i * 4 + 3] = f.w;
            }
            float mloc = v[0];
#pragma unroll
            for (int i = 1; i < 32; i++) mloc = fmaxf(mloc, v[i]);
            mloc = fmaxf(mloc, __shfl_xor_sync(0xffffffffu, mloc, 1));
            const float mold = smM[row];
            const float mx = fmaxf(mold, mloc);
            const float alpha = __expf(mold - mx);
            float sum = 0.f;
            __nv_bfloat162* dh = (__nv_bfloat162*)(sm + FA_PH + row * VROWB + seg * 64);
            __nv_bfloat162* dl = (__nv_bfloat162*)(sm + FA_PL + row * VROWB + seg * 64);
#pragma unroll
            for (int i = 0; i < 16; i++) {
                float p0 = __expf(v[2 * i]     - mx);
                float p1 = __expf(v[2 * i + 1] - mx);
                sum += p0 + p1;
                __nv_bfloat16 h0 = __float2bfloat16(p0);
                __nv_bfloat16 h1 = __float2bfloat16(p1);
                dh[i] = __nv_bfloat162(h0, h1);
                dl[i] = __nv_bfloat162(__float2bfloat16(p0 - __bfloat162float(h0)),
                                       __float2bfloat16(p1 - __bfloat162float(h1)));
            }
            sum += __shfl_xor_sync(0xffffffffu, sum, 1);
            if (seg == 0) {
                smM[row] = mx;
                smL[row] = smL[row] * alpha + sum;
                smA[row] = alpha;
            }
        }
        __syncthreads();

        {
            const float a0 = smA[wid * 16 + r0];
            const float a1 = smA[wid * 16 + r0 + 8];
#pragma unroll
            for (int g = 0; g < 16; g++) {
                oa[g][0] *= a0; oa[g][1] *= a0;
                oa[g][2] *= a1; oa[g][3] *= a1;
            }
        }
#pragma unroll
        for (int kk = 0; kk < 4; kk++) {
            uint32_t pa = sb + FA_PH + (wid * 16 + lrow16) * VROWB + kk * 32 + lhalf;
            uint32_t ph[4], pl[4];
            ldsm_x4(pa,                   ph[0], ph[1], ph[2], ph[3]);
            ldsm_x4(pa + (FA_PL - FA_PH), pl[0], pl[1], pl[2], pl[3]);
#pragma unroll
            for (int g = 0; g < 8; g++) {
                uint32_t va = vbS + (g * 16 + lrow16) * VROWB + kk * 32 + lhalf;
                uint32_t vh0, vh1, vh2, vh3, vl0, vl1, vl2, vl3;
                ldsm_x4(va,         vh0, vh1, vh2, vh3);
                ldsm_x4(va + 18432, vl0, vl1, vl2, vl3);
                mma_bf16(oa[g * 2],     ph, vh0, vh2);
                mma_bf16(oa[g * 2 + 1], ph, vh1, vh3);
                mma_bf16(oa[g * 2],     ph, vl0, vl2);
                mma_bf16(oa[g * 2 + 1], ph, vl1, vl3);
                mma_bf16(oa[g * 2],     pl, vh0, vh2);
                mma_bf16(oa[g * 2 + 1], pl, vh1, vh3);
            }
        }
        __syncthreads();
        if (kt + 2 < NKT) issue(kt + 2);
    }

    // ---- epilogue: O/l -> fp16 U/W global (input to O-projection) ----
    const float inv0 = 1.0f / smL[wid * 16 + r0];
    const float inv1 = 1.0f / smL[wid * 16 + r0 + 8];
    const int row0 = qt * 128 + wid * 16 + r0;
#pragma unroll
    for (int g = 0; g < 16; g++) {
        const int col = (g >> 1) * 16 + (g & 1) * 8 + c2;
        const size_t i0 = (size_t)row0 * DIM + h * HD + col;
        const size_t i1 = (size_t)(row0 + 8) * DIM + h * HD + col;
        float v0 = oa[g][0] * inv0, v1 = oa[g][1] * inv0;
        float v2 = oa[g][2] * inv1, v3 = oa[g][3] * inv1;
        __half u0, w0, u1, w1, u2, w2, u3, w3;
        uw_split(v0, u0, w0); uw_split(v1, u1, w1);
        uw_split(v2, u2, w2); uw_split(v3, u3, w3);
        *(__half2*)(ou + i0) = __halves2half2(u0, u1);
        *(__half2*)(ou + i1) = __halves2half2(u2, u3);
        *(__half2*)(ow + i0) = __halves2half2(w0, w1);
        *(__half2*)(ow + i1) = __halves2half2(w2, w3);
    }
}

// ---------------- launch ---------------------------------------------------
template <typename T>
static T* symaddr(const void* sym)
{
    void* p = nullptr;
    cudaGetSymbolAddress(&p, sym);
    return (T*)p;
}

extern "C" void kernel_launch(void* const* d_in, const int* in_sizes, int n_in,
                              void* d_out, int out_size)
{
    const float* x       = (const float*)d_in[0];
    const float* wq      = (const float*)d_in[1];
    const float* bq      = (const float*)d_in[2];
    const float* wk      = (const float*)d_in[3];
    const float* bk      = (const float*)d_in[4];
    const float* wv      = (const float*)d_in[5];
    const float* bv      = (const float*)d_in[6];
    const float* wo      = (const float*)d_in[7];
    const float* bo      = (const float*)d_in[8];
    const float* lq_down = (const float*)d_in[9];
    const float* lq_up   = (const float*)d_in[10];
    const float* lk_down = (const float*)d_in[11];
    const float* lk_up   = (const float*)d_in[12];
    const float* lv_down = (const float*)d_in[13];
    const float* lv_up   = (const float*)d_in[14];
    const float* lo_down = (const float*)d_in[15];
    const float* lo_up   = (const float*)d_in[16];
    const float* nq_w    = (const float*)d_in[17];
    const float* nk_w    = (const float*)d_in[18];
    const float* fcos    = (const float*)d_in[19];
    const float* fsin    = (const float*)d_in[20];

    __half* xu = symaddr<__half>(g_xu);
    __half* xw = symaddr<__half>(g_xw);
    __half* wu = symaddr<__half>(g_wu);
    __half* ww = symaddr<__half>(g_ww);
    __half* ou = symaddr<__half>(g_ou);
    __half* ow = symaddr<__half>(g_ow);
    __nv_bfloat16* qhi = symaddr<__nv_bfloat16>(g_qhi);
    __nv_bfloat16* qlo = symaddr<__nv_bfloat16>(g_qlo);
    __nv_bfloat16* khi = symaddr<__nv_bfloat16>(g_khi);
    __nv_bfloat16* klo = symaddr<__nv_bfloat16>(g_klo);
    __nv_bfloat16* vthi = symaddr<__nv_bfloat16>(g_vthi);
    __nv_bfloat16* vtlo = symaddr<__nv_bfloat16>(g_vtlo);
    float* q = symaddr<float>(g_q);
    float* k = symaddr<float>(g_k);
    float* v = symaddr<float>(g_v);

    cudaFuncSetAttribute(gemm_hmma, cudaFuncAttributeMaxDynamicSharedMemorySize,
                         GEMM_SMEM);
    cudaFuncSetAttribute(flash_attn_tc, cudaFuncAttributeMaxDynamicSharedMemorySize,
                         FA_SMEM);

    const float scale = 16.0f / (float)RANK;   // ALPHA / R = 1.0
    const int   nel   = SEQ * DIM;
    const size_t WSZ  = (size_t)DIM * DIM;

    // 1) U/W splits + effective weights
    split_uw<<<(nel + 255) / 256, 256>>>(x, xu, xw, nel);
    PrepBatch pb;
    pb.w[0] = wq; pb.w[1] = wk; pb.w[2] = wv; pb.w[3] = wo;
    pb.ld[0] = lq_down; pb.ld[1] = lk_down; pb.ld[2] = lv_down; pb.ld[3] = lo_down;
    pb.lu[0] = lq_up;   pb.lu[1] = lk_up;   pb.lu[2] = lv_up;   pb.lu[3] = lo_up;
    for (int i = 0; i < 4; i++) { pb.U[i] = wu + i * WSZ; pb.W[i] = ww + i * WSZ; }
    prep_weff_split<<<dim3(DIM / 256, DIM, 4), 256>>>(pb, scale);

    // 2) QKV projections: batched fp16 2-MMA GEMM
    GemmBatch gqkv;
    gqkv.bu[0] = wu + 0 * WSZ; gqkv.bu[1] = wu + 1 * WSZ; gqkv.bu[2] = wu + 2 * WSZ;
    gqkv.bw[0] = ww + 0 * WSZ; gqkv.bw[1] = ww + 1 * WSZ; gqkv.bw[2] = ww + 2 * WSZ;
    gqkv.bias[0] = bq; gqkv.bias[1] = bk; gqkv.bias[2] = bv;
    gqkv.out[0] = q; gqkv.out[1] = k; gqkv.out[2] = v;
    gemm_hmma<<<dim3(DIM / 128, SEQ / 128, 3), 256, GEMM_SMEM>>>(xu, xw, gqkv);

    // 3) norm+rope -> bf16 splits; V transpose-split (attention inputs)
    NormBatch nb;
    nb.X[0] = q; nb.X[1] = k;
    nb.w[0] = nq_w; nb.w[1] = nk_w;
    nb.hi[0] = qhi; nb.hi[1] = khi;
    nb.lo[0] = qlo; nb.lo[1] = klo;
    nb.outscale[0] = 0.08838834764831845f; nb.outscale[1] = 1.0f;
    rmsnorm_rope_split<<<dim3(SEQ, 2), 256>>>(nb, fcos, fsin);
    vtrans_split<<<dim3(SEQ / 32, HD / 32, NH), dim3(32, 8)>>>(v, vthi, vtlo);

    // 4) tensor-core flash attention -> fp16 U/W O
    flash_attn_tc<<<dim3(SEQ / 128, NH), 256, FA_SMEM>>>(qhi, qlo, khi, klo,
                                                         vthi, vtlo, ou, ow);

    // 5) output projection (fp16 2-MMA GEMM)
    GemmBatch go;
    go.bu[0] = wu + 3 * WSZ; go.bu[1] = nullptr; go.bu[2] = nullptr;
    go.bw[0] = ww + 3 * WSZ; go.bw[1] = nullptr; go.bw[2] = nullptr;
    go.bias[0] = bo; go.bias[1] = nullptr; go.bias[2] = nullptr;
    go.out[0] = (float*)d_out; go.out[1] = nullptr; go.out[2] = nullptr;
    gemm_hmma<<<dim3(DIM / 128, SEQ / 128, 1), 256, GEMM_SMEM>>>(ou, ow, go);
}

// round 17
// speedup vs baseline: 1.2366x; 1.0379x over previous
#include <cuda_runtime.h>
#include <cuda_bf16.h>
#include <cuda_fp16.h>
#include <math.h>
#include <stdint.h>

#define DIM   2048
#define SEQ   3072
#define NH    16
#define HD    128
#define RANK  16
#define EPS_  1e-6f

// ---------------- scratch (static device memory; no allocs) ----------------
__device__ __half g_xu[SEQ * DIM];
__device__ __half g_xw[SEQ * DIM];
__device__ __half g_wu[4][DIM * DIM];
__device__ __half g_ww[4][DIM * DIM];
__device__ __half g_ou[SEQ * DIM];
__device__ __half g_ow[SEQ * DIM];
__device__ __half g_qu[SEQ * DIM];
__device__ __half g_qw[SEQ * DIM];
__device__ __half g_ku[SEQ * DIM];
__device__ __half g_kw[SEQ * DIM];
__device__ __nv_bfloat16 g_vthi[NH * HD * SEQ];
__device__ __nv_bfloat16 g_vtlo[NH * HD * SEQ];
__device__ float g_q[SEQ * DIM];
__device__ float g_k[SEQ * DIM];
__device__ float g_v[SEQ * DIM];

// ---------------- PTX helpers ---------------------------------------------
__device__ __forceinline__ uint32_t smem_u32(const void* p)
{
    uint32_t a;
    asm("{ .reg .u64 t; cvta.to.shared.u64 t, %1; cvt.u32.u64 %0, t; }"
        : "=r"(a) : "l"(p));
    return a;
}

__device__ __forceinline__ void cp_async16(uint32_t s, const void* g)
{
    asm volatile("cp.async.cg.shared.global [%0], [%1], 16;" :: "r"(s), "l"(g));
}

__device__ __forceinline__ void cp_commit()
{
    asm volatile("cp.async.commit_group;" ::: "memory");
}

template <int N>
__device__ __forceinline__ void cp_wait()
{
    asm volatile("cp.async.wait_group %0;" :: "n"(N) : "memory");
}

__device__ __forceinline__ void ldsm_x4(uint32_t addr, uint32_t& r0, uint32_t& r1,
                                        uint32_t& r2, uint32_t& r3)
{
    asm volatile("ldmatrix.sync.aligned.m8n8.x4.shared.b16 {%0,%1,%2,%3}, [%4];"
                 : "=r"(r0), "=r"(r1), "=r"(r2), "=r"(r3) : "r"(addr));
}

__device__ __forceinline__ void mma_bf16(float* c,
                                         const uint32_t* a, uint32_t b0, uint32_t b1)
{
    asm volatile(
        "mma.sync.aligned.m16n8k16.row.col.f32.bf16.bf16.f32 "
        "{%0,%1,%2,%3}, {%4,%5,%6,%7}, {%8,%9}, {%0,%1,%2,%3};"
        : "+f"(c[0]), "+f"(c[1]), "+f"(c[2]), "+f"(c[3])
        : "r"(a[0]), "r"(a[1]), "r"(a[2]), "r"(a[3]), "r"(b0), "r"(b1));
}

__device__ __forceinline__ void mma_fp16(float* c,
                                         const uint32_t* a, uint32_t b0, uint32_t b1)
{
    asm volatile(
        "mma.sync.aligned.m16n8k16.row.col.f32.f16.f16.f32 "
        "{%0,%1,%2,%3}, {%4,%5,%6,%7}, {%8,%9}, {%0,%1,%2,%3};"
        : "+f"(c[0]), "+f"(c[1]), "+f"(c[2]), "+f"(c[3])
        : "r"(a[0]), "r"(a[1]), "r"(a[2]), "r"(a[3]), "r"(b0), "r"(b1));
}

// u = fp16(v); w = fp16(u + 32*(v-u)) = fp16(32v - 31u)
__device__ __forceinline__ void uw_split(float v, __half& u, __half& w)
{
    u = __float2half_rn(v);
    float uf = __half2float(u);
    w = __float2half_rn(fmaf(32.f, v, -31.f * uf));
}

// ---------------- batched param structs ------------------------------------
struct PrepBatch {
    const float* w[4];
    const float* ld[4];
    const float* lu[4];
    __half* U[4];
    __half* W[4];
};

struct GemmBatch {
    const __half* bu[3];
    const __half* bw[3];
    const float* bias[3];
    float* out[3];
};

struct NormBatch {
    const float* X[2];
    const float* w[2];
    __half* U[2];
    __half* W[2];
    float outscale[2];
};

// ---------------- 1) effective weight prep + fp16 U/W split ----------------
__global__ __launch_bounds__(256) void prep_weff_split(PrepBatch P, float scale)
{
    const int z  = blockIdx.z;
    const int kx = blockIdx.x * 256 + threadIdx.x;
    const int j  = blockIdx.y;
    const float* lu = P.lu[z];
    const float* ld = P.ld[z];
    float acc = 0.f;
#pragma unroll
    for (int r = 0; r < RANK; r++)
        acc += lu[j * RANK + r] * ld[r * DIM + kx];
    float v = P.w[z][j * DIM + kx] + scale * acc;
    __half u, w;
    uw_split(v, u, w);
    P.U[z][j * DIM + kx] = u;
    P.W[z][j * DIM + kx] = w;
}

// ---------------- 2) fp32 -> fp16 U/W split ---------------------------------
__global__ __launch_bounds__(256) void split_uw(const float* __restrict__ in,
                                                __half* __restrict__ U,
                                                __half* __restrict__ W,
                                                int n)
{
    int i = blockIdx.x * 256 + threadIdx.x;
    if (i < n) {
        __half u, w;
        uw_split(in[i], u, w);
        U[i] = u;
        W[i] = w;
    }
}

// ---------------- 3) fp16 2-MMA emulated-fp32 NT GEMM (128x128, 2-stage) ----
#define KC        32
#define ROWB      80
#define TILEB     (128 * ROWB)             // 10240
#define STAGEB    (4 * TILEB)              // 40960
#define GEMM_SMEM (2 * STAGEB)             // 81920 -> 2 CTA/SM

__global__ __launch_bounds__(256) void gemm_hmma(const __half* __restrict__ Au,
                                                 const __half* __restrict__ Aw,
                                                 GemmBatch P)
{
    extern __shared__ __align__(128) char sm[];
    const uint32_t sbase = smem_u32(sm);

    const int tid  = threadIdx.x;
    const int wid  = tid >> 5;
    const int lane = tid & 31;
    const int zz = blockIdx.z;
    const int m0 = blockIdx.y * 128;
    const int n0 = blockIdx.x * 128;
    const int wm = wid & 3;
    const int wn = wid >> 2;

    const __half* Bu = P.bu[zz];
    const __half* Bw = P.bw[zz];
    const float* bias = P.bias[zz];
    float* C = P.out[zz];

    const int lrow = tid >> 1;
    const int lcp  = (tid & 1) * 2;
    const uint32_t srow = sbase + (uint32_t)lrow * ROWB + (uint32_t)lcp * 16;
    const __half* gAu = Au + (size_t)(m0 + lrow) * DIM + lcp * 8;
    const __half* gAw = Aw + (size_t)(m0 + lrow) * DIM + lcp * 8;
    const __half* gBu = Bu + (size_t)(n0 + lrow) * DIM + lcp * 8;
    const __half* gBw = Bw + (size_t)(n0 + lrow) * DIM + lcp * 8;

    float accC[2][8][4], accD[2][8][4];
#pragma unroll
    for (int i = 0; i < 2; i++)
#pragma unroll
        for (int j = 0; j < 8; j++)
#pragma unroll
            for (int e = 0; e < 4; e++) { accC[i][j][e] = 0.f; accD[i][j][e] = 0.f; }

    const int NCH = DIM / KC;

    auto issue = [&](int c) {
        uint32_t b = srow + (uint32_t)(c & 1) * STAGEB;
        const int ko = c * KC;
        cp_async16(b + 0 * TILEB,      gAu + ko);
        cp_async16(b + 0 * TILEB + 16, gAu + ko + 8);
        cp_async16(b + 1 * TILEB,      gAw + ko);
        cp_async16(b + 1 * TILEB + 16, gAw + ko + 8);
        cp_async16(b + 2 * TILEB,      gBu + ko);
        cp_async16(b + 2 * TILEB + 16, gBu + ko + 8);
        cp_async16(b + 3 * TILEB,      gBw + ko);
        cp_async16(b + 3 * TILEB + 16, gBw + ko + 8);
        cp_commit();
    };

    issue(0);
    issue(1);

    const uint32_t lrow16 = (uint32_t)(lane & 15);
    const uint32_t lhalf  = (uint32_t)(lane >> 4) * 16;

    for (int c = 0; c < NCH; c++) {
        if (c == NCH - 1) cp_wait<0>(); else cp_wait<1>();
        __syncthreads();

        const uint32_t st = sbase + (uint32_t)(c & 1) * STAGEB;
        const uint32_t aRow = st + (uint32_t)(wm * 32) * ROWB;
        const uint32_t bRow = st + 2 * TILEB + (uint32_t)(wn * 64) * ROWB;

#pragma unroll
        for (int ks = 0; ks < 2; ks++) {
            const uint32_t kb = (uint32_t)(ks * 32) + lhalf;

            uint32_t uA[2][4], wA[2][4];
#pragma unroll
            for (int im = 0; im < 2; im++) {
                uint32_t ra = aRow + (im * 16 + lrow16) * ROWB + kb;
                ldsm_x4(ra,         uA[im][0], uA[im][1], uA[im][2], uA[im][3]);
                ldsm_x4(ra + TILEB, wA[im][0], wA[im][1], wA[im][2], wA[im][3]);
            }

#pragma unroll
            for (int in4 = 0; in4 < 4; in4++) {
                uint32_t rb = bRow + (in4 * 16 + lrow16) * ROWB + kb;
                uint32_t bu0, bu1, bu2, bu3, bw0, bw1, bw2, bw3;
                ldsm_x4(rb,         bu0, bu1, bu2, bu3);
                ldsm_x4(rb + TILEB, bw0, bw1, bw2, bw3);

#pragma unroll
                for (int im = 0; im < 2; im++) {
                    mma_fp16(accC[im][in4 * 2],     uA[im], bu0, bu2);
                    mma_fp16(accC[im][in4 * 2 + 1], uA[im], bu1, bu3);
                    mma_fp16(accD[im][in4 * 2],     wA[im], bw0, bw2);
                    mma_fp16(accD[im][in4 * 2 + 1], wA[im], bw1, bw3);
                }
            }
        }
        __syncthreads();
        if (c + 2 < NCH) issue(c + 2);
    }

    const int r0 = lane >> 2;
    const int cpair = (lane & 3) * 2;
#pragma unroll
    for (int im = 0; im < 2; im++) {
        const int mrow = m0 + wm * 32 + im * 16 + r0;
#pragma unroll
        for (int jn = 0; jn < 8; jn++) {
            const int col = n0 + wn * 64 + jn * 8 + cpair;
            const float b0 = bias[col], b1 = bias[col + 1];
            float* cc = accC[im][jn];
            float* dd = accD[im][jn];
            float v0 = cc[0] + (dd[0] - cc[0]) * 0.03125f + b0;
            float v1 = cc[1] + (dd[1] - cc[1]) * 0.03125f + b1;
            float v2 = cc[2] + (dd[2] - cc[2]) * 0.03125f + b0;
            float v3 = cc[3] + (dd[3] - cc[3]) * 0.03125f + b1;
            float* p0 = C + (size_t)mrow * DIM + col;
            float* p1 = C + (size_t)(mrow + 8) * DIM + col;
            *(float2*)p0 = make_float2(v0, v1);
            *(float2*)p1 = make_float2(v2, v3);
        }
    }
}

// ---------------- 4) RMSNorm + RoPE + fp16 U/W split (batched q/k) ---------
__global__ __launch_bounds__(256) void rmsnorm_rope_split(NormBatch P,
                                                          const float* __restrict__ fcos,
                                                          const float* __restrict__ fsin)
{
    const int z = blockIdx.y;
    const int s = blockIdx.x;
    const int tid = threadIdx.x;
    __shared__ float red[256];

    const float* row = P.X[z] + (size_t)s * DIM;
    const float* w = P.w[z];
    __half* U = P.U[z];
    __half* W = P.W[z];
    const float outscale = P.outscale[z];

    float ss = 0.f;
#pragma unroll
    for (int i = tid; i < DIM; i += 256) { float v = row[i]; ss += v * v; }
    red[tid] = ss;
    __syncthreads();
    for (int st = 128; st > 0; st >>= 1) {
        if (tid < st) red[tid] += red[tid + st];
        __syncthreads();
    }
    const float rs = rsqrtf(red[0] / (float)DIM + EPS_);

#pragma unroll
    for (int p = tid; p < DIM / 2; p += 256) {
        int hp = p & 63;
        float c  = fcos[s * HD + 2 * hp];
        float sn = fsin[s * HD + 2 * hp + 1];
        float x1 = row[2 * p]     * rs * w[2 * p];
        float x2 = row[2 * p + 1] * rs * w[2 * p + 1];
        float e = (x1 * c - x2 * sn) * outscale;
        float o = (x1 * sn + x2 * c) * outscale;
        __half eu, ew, ou_, ow_;
        uw_split(e, eu, ew);
        uw_split(o, ou_, ow_);
        U[(size_t)s * DIM + 2 * p]     = eu;
        U[(size_t)s * DIM + 2 * p + 1] = ou_;
        W[(size_t)s * DIM + 2 * p]     = ew;
        W[(size_t)s * DIM + 2 * p + 1] = ow_;
    }
}

// ---------------- 5) V transpose + split: [s][h*128+d] -> [h][d][s] --------
__global__ __launch_bounds__(256) void vtrans_split(const float* __restrict__ V,
                                                    __nv_bfloat16* __restrict__ vthi,
                                                    __nv_bfloat16* __restrict__ vtlo)
{
    __shared__ float t[32][33];
    const int s0 = blockIdx.x * 32;
    const int d0 = blockIdx.y * 32;
    const int h  = blockIdx.z;
    const int tx = threadIdx.x;
    const int ty = threadIdx.y;

    for (int i = ty; i < 32; i += 8)
        t[i][tx] = V[(size_t)(s0 + i) * DIM + h * HD + d0 + tx];
    __syncthreads();
    for (int i = ty; i < 32; i += 8) {
        float v = t[tx][i];
        __nv_bfloat16 hv = __float2bfloat16(v);
        size_t idx = (size_t)h * HD * SEQ + (size_t)(d0 + i) * SEQ + s0 + tx;
        vthi[idx] = hv;
        vtlo[idx] = __float2bfloat16(v - __bfloat162float(hv));
    }
}

// ---------------- 6) flash attention: fp16 U/W QK, bf16 3-MMA PV -----------
// CTA: 128 q-rows x 1 head, 256 threads = 8 warps, warp = 16 q-rows.
#define FA_KB   0
#define FA_VB   69632
#define FA_SS   143360
#define FA_PH   178176
#define FA_PL   196608
#define FA_MM   215040
#define FA_LL   215552
#define FA_AA   216064
#define FA_SMEM 216576
#define KROWB   272
#define VROWB   144
#define NKT     (SEQ / 64)

__global__ __launch_bounds__(256, 1) void flash_attn_tc(
    const __half* __restrict__ qu, const __half* __restrict__ qw,
    const __half* __restrict__ ku, const __half* __restrict__ kw,
    const __nv_bfloat16* __restrict__ vthi, const __nv_bfloat16* __restrict__ vtlo,
    __half* __restrict__ ou, __half* __restrict__ ow)
{
    extern __shared__ __align__(128) char sm[];
    const uint32_t sb = smem_u32(sm);
    const int tid  = threadIdx.x;
    const int wid  = tid >> 5;
    const int lane = tid & 31;
    const int qt = blockIdx.x;
    const int h  = blockIdx.y;
    const uint32_t lrow16 = (uint32_t)(lane & 15);
    const uint32_t lhalf  = (uint32_t)(lane >> 4) * 16;
    const int r0 = lane >> 2;
    const int c2 = (lane & 3) * 2;

    float* smM = (float*)(sm + FA_MM);
    float* smL = (float*)(sm + FA_LL);
    float* smA = (float*)(sm + FA_AA);

    // ---- stage Q (u then w) through FA_SS, hold fragments in registers ----
    uint32_t qU[8][4], qW[8][4];
    const size_t qoff = (size_t)(qt * 128) * DIM + h * HD;
#pragma unroll
    for (int pass = 0; pass < 2; pass++) {
        const __half* src = (pass == 0) ? (qu + qoff) : (qw + qoff);
        for (int c = tid; c < 2048; c += 256) {
            int row = c >> 4, o16 = c & 15;
            *(uint4*)(sm + FA_SS + row * KROWB + o16 * 16) =
                *(const uint4*)(src + (size_t)row * DIM + o16 * 8);
        }
        __syncthreads();
#pragma unroll
        for (int kk = 0; kk < 8; kk++) {
            uint32_t ra = sb + FA_SS + (wid * 16 + lrow16) * KROWB + kk * 32 + lhalf;
            if (pass == 0) ldsm_x4(ra, qU[kk][0], qU[kk][1], qU[kk][2], qU[kk][3]);
            else           ldsm_x4(ra, qW[kk][0], qW[kk][1], qW[kk][2], qW[kk][3]);
        }
        __syncthreads();
    }
    if (tid < 128) { smM[tid] = -1e30f; smL[tid] = 0.f; }

    float oa[16][4];
#pragma unroll
    for (int g = 0; g < 16; g++)
#pragma unroll
        for (int e = 0; e < 4; e++) oa[g][e] = 0.f;

    auto issue = [&](int kt) {
        const uint32_t stg = (uint32_t)(kt & 1);
        for (int i = 0; i < 4; i++) {
            int c = tid + i * 256;
            int row = c >> 4, o16 = c & 15;
            const size_t g = (size_t)(kt * 64 + row) * DIM + h * HD + o16 * 8;
            uint32_t d = sb + FA_KB + stg * 34816 + row * KROWB + o16 * 16;
            cp_async16(d,         ku + g);
            cp_async16(d + 17408, kw + g);
        }
        for (int i = 0; i < 4; i++) {
            int c = tid + i * 256;
            int row = c >> 3, o16 = c & 7;
            const size_t g = (size_t)h * HD * SEQ + (size_t)row * SEQ + kt * 64 + o16 * 8;
            uint32_t d = sb + FA_VB + stg * 36864 + row * VROWB + o16 * 16;
            cp_async16(d,         vthi + g);
            cp_async16(d + 18432, vtlo + g);
        }
        cp_commit();
    };

    issue(0);
    issue(1);

    for (int kt = 0; kt < NKT; kt++) {
        if (kt == NKT - 1) cp_wait<0>(); else cp_wait<1>();
        __syncthreads();
        const uint32_t kbS = sb + FA_KB + (uint32_t)(kt & 1) * 34816;
        const uint32_t vbS = sb + FA_VB + (uint32_t)(kt & 1) * 36864;

        // ---- S = Q K^T via 2-MMA U/W: C += Qu Ku, D += Qw Kw ----
        float sC[8][4], sD[8][4];
#pragma unroll
        for (int g = 0; g < 8; g++)
#pragma unroll
            for (int e = 0; e < 4; e++) { sC[g][e] = 0.f; sD[g][e] = 0.f; }

#pragma unroll
        for (int kk = 0; kk < 8; kk++) {
#pragma unroll
            for (int j = 0; j < 4; j++) {
                uint32_t ra = kbS + (j * 16 + lrow16) * KROWB + kk * 32 + lhalf;
                uint32_t ku0, ku1, ku2, ku3, kw0, kw1, kw2, kw3;
                ldsm_x4(ra,         ku0, ku1, ku2, ku3);
                ldsm_x4(ra + 17408, kw0, kw1, kw2, kw3);
                mma_fp16(sC[j * 2],     qU[kk], ku0, ku2);
                mma_fp16(sC[j * 2 + 1], qU[kk], ku1, ku3);
                mma_fp16(sD[j * 2],     qW[kk], kw0, kw2);
                mma_fp16(sD[j * 2 + 1], qW[kk], kw1, kw3);
            }
        }
#pragma unroll
        for (int g = 0; g < 8; g++) {
            int col = (g >> 1) * 16 + (g & 1) * 8 + c2;
            int row = wid * 16 + r0;
            float m0 = sC[g][0] + (sD[g][0] - sC[g][0]) * 0.03125f;
            float m1 = sC[g][1] + (sD[g][1] - sC[g][1]) * 0.03125f;
            float m2 = sC[g][2] + (sD[g][2] - sC[g][2]) * 0.03125f;
            float m3 = sC[g][3] + (sD[g][3] - sC[g][3]) * 0.03125f;
            *(float2*)(sm + FA_SS + row * KROWB + col * 4)       = make_float2(m0, m1);
            *(float2*)(sm + FA_SS + (row + 8) * KROWB + col * 4) = make_float2(m2, m3);
        }
        __syncthreads();

        // ---- online softmax: 2 threads per row, 32 cols each ----
        {
            const int row = tid >> 1, seg = tid & 1;
            const float* sr = (const float*)(sm + FA_SS + row * KROWB + seg * 128);
            float v[32];
#pragma unroll
            for (int i = 0; i < 8; i++) {
                float4 f = *(const float4*)(sr + i * 4);
                v[i * 4] = f.x; v[i * 4 + 1] = f.y; v[i * 4 + 2] = f.z; v[i * 4 + 3] = f.w;
            }
            float mloc = v[0];
#pragma unroll
            for (int i = 1; i < 32; i++) mloc = fmaxf(mloc, v[i]);
            mloc = fmaxf(mloc, __shfl_xor_sync(0xffffffffu, mloc, 1));
            const float mold = smM[row];
            const float mx = fmaxf(mold, mloc);
            const float alpha = __expf(mold - mx);
            float sum = 0.f;
            __nv_bfloat162* dh = (__nv_bfloat162*)(sm + FA_PH + row * VROWB + seg * 64);
            __nv_bfloat162* dl = (__nv_bfloat162*)(sm + FA_PL + row * VROWB + seg * 64);
#pragma unroll
            for (int i = 0; i < 16; i++) {
                float p0 = __expf(v[2 * i]     - mx);
                float p1 = __expf(v[2 * i + 1] - mx);
                sum += p0 + p1;
                __nv_bfloat16 h0 = __float2bfloat16(p0);
                __nv_bfloat16 h1 = __float2bfloat16(p1);
                dh[i] = __nv_bfloat162(h0, h1);
                dl[i] = __nv_bfloat162(__float2bfloat16(p0 - __bfloat162float(h0)),
                                       __float2bfloat16(p1 - __bfloat162float(h1)));
            }
            sum += __shfl_xor_sync(0xffffffffu, sum, 1);
            if (seg == 0) {
                smM[row] = mx;
                smL[row] = smL[row] * alpha + sum;
                smA[row] = alpha;
            }
        }
        __syncthreads();

        // ---- rescale O, then O += P V (bf16 3-MMA) ----
        {
            const float a0 = smA[wid * 16 + r0];
            const float a1 = smA[wid * 16 + r0 + 8];
#pragma unroll
            for (int g = 0; g < 16; g++) {
                oa[g][0] *= a0; oa[g][1] *= a0;
                oa[g][2] *= a1; oa[g][3] *= a1;
            }
        }
#pragma unroll
        for (int kk = 0; kk < 4; kk++) {
            uint32_t pa = sb + FA_PH + (wid * 16 + lrow16) * VROWB + kk * 32 + lhalf;
            uint32_t ph[4], pl[4];
            ldsm_x4(pa,                   ph[0], ph[1], ph[2], ph[3]);
            ldsm_x4(pa + (FA_PL - FA_PH), pl[0], pl[1], pl[2], pl[3]);
#pragma unroll
            for (int g = 0; g < 8; g++) {
                uint32_t va = vbS + (g * 16 + lrow16) * VROWB + kk * 32 + lhalf;
                uint32_t vh0, vh1, vh2, vh3, vl0, vl1, vl2, vl3;
                ldsm_x4(va,         vh0, vh1, vh2, vh3);
                ldsm_x4(va + 18432, vl0, vl1, vl2, vl3);
                mma_bf16(oa[g * 2],     ph, vh0, vh2);
                mma_bf16(oa[g * 2 + 1], ph, vh1, vh3);
                mma_bf16(oa[g * 2],     ph, vl0, vl2);
                mma_bf16(oa[g * 2 + 1], ph, vl1, vl3);
                mma_bf16(oa[g * 2],     pl, vh0, vh2);
                mma_bf16(oa[g * 2 + 1], pl, vh1, vh3);
            }
        }
        __syncthreads();
        if (kt + 2 < NKT) issue(kt + 2);
    }

    // ---- epilogue: O/l -> fp16 U/W global (input to O-projection) ----
    const float inv0 = 1.0f / smL[wid * 16 + r0];
    const float inv1 = 1.0f / smL[wid * 16 + r0 + 8];
    const int row0 = qt * 128 + wid * 16 + r0;
#pragma unroll
    for (int g = 0; g < 16; g++) {
        const int col = (g >> 1) * 16 + (g & 1) * 8 + c2;
        const size_t i0 = (size_t)row0 * DIM + h * HD + col;
        const size_t i1 = (size_t)(row0 + 8) * DIM + h * HD + col;
        float v0 = oa[g][0] * inv0, v1 = oa[g][1] * inv0;
        float v2 = oa[g][2] * inv1, v3 = oa[g][3] * inv1;
        __half u0, w0, u1, w1, u2, w2, u3, w3;
        uw_split(v0, u0, w0); uw_split(v1, u1, w1);
        uw_split(v2, u2, w2); uw_split(v3, u3, w3);
        *(__half2*)(ou + i0) = __halves2half2(u0, u1);
        *(__half2*)(ou + i1) = __halves2half2(u2, u3);
        *(__half2*)(ow + i0) = __halves2half2(w0, w1);
        *(__half2*)(ow + i1) = __halves2half2(w2, w3);
    }
}

// ---------------- launch ---------------------------------------------------
template <typename T>
static T* symaddr(const void* sym)
{
    void* p = nullptr;
    cudaGetSymbolAddress(&p, sym);
    return (T*)p;
}

extern "C" void kernel_launch(void* const* d_in, const int* in_sizes, int n_in,
                              void* d_out, int out_size)
{
    const float* x       = (const float*)d_in[0];
    const float* wq      = (const float*)d_in[1];
    const float* bq      = (const float*)d_in[2];
    const float* wk      = (const float*)d_in[3];
    const float* bk      = (const float*)d_in[4];
    const float* wv      = (const float*)d_in[5];
    const float* bv      = (const float*)d_in[6];
    const float* wo      = (const float*)d_in[7];
    const float* bo      = (const float*)d_in[8];
    const float* lq_down = (const float*)d_in[9];
    const float* lq_up   = (const float*)d_in[10];
    const float* lk_down = (const float*)d_in[11];
    const float* lk_up   = (const float*)d_in[12];
    const float* lv_down = (const float*)d_in[13];
    const float* lv_up   = (const float*)d_in[14];
    const float* lo_down = (const float*)d_in[15];
    const float* lo_up   = (const float*)d_in[16];
    const float* nq_w    = (const float*)d_in[17];
    const float* nk_w    = (const float*)d_in[18];
    const float* fcos    = (const float*)d_in[19];
    const float* fsin    = (const float*)d_in[20];

    __half* xu = symaddr<__half>(g_xu);
    __half* xw = symaddr<__half>(g_xw);
    __half* wu = symaddr<__half>(g_wu);
    __half* ww = symaddr<__half>(g_ww);
    __half* ou = symaddr<__half>(g_ou);
    __half* ow = symaddr<__half>(g_ow);
    __half* quP = symaddr<__half>(g_qu);
    __half* qwP = symaddr<__half>(g_qw);
    __half* kuP = symaddr<__half>(g_ku);
    __half* kwP = symaddr<__half>(g_kw);
    __nv_bfloat16* vthi = symaddr<__nv_bfloat16>(g_vthi);
    __nv_bfloat16* vtlo = symaddr<__nv_bfloat16>(g_vtlo);
    float* q = symaddr<float>(g_q);
    float* k = symaddr<float>(g_k);
    float* v = symaddr<float>(g_v);

    cudaFuncSetAttribute(gemm_hmma, cudaFuncAttributeMaxDynamicSharedMemorySize,
                         GEMM_SMEM);
    cudaFuncSetAttribute(flash_attn_tc, cudaFuncAttributeMaxDynamicSharedMemorySize,
                         FA_SMEM);

    const float scale = 16.0f / (float)RANK;   // ALPHA / R = 1.0
    const int   nel   = SEQ * DIM;
    const size_t WSZ  = (size_t)DIM * DIM;

    // 1) U/W splits + effective weights
    split_uw<<<(nel + 255) / 256, 256>>>(x, xu, xw, nel);
    PrepBatch pb;
    pb.w[0] = wq; pb.w[1] = wk; pb.w[2] = wv; pb.w[3] = wo;
    pb.ld[0] = lq_down; pb.ld[1] = lk_down; pb.ld[2] = lv_down; pb.ld[3] = lo_down;
    pb.lu[0] = lq_up;   pb.lu[1] = lk_up;   pb.lu[2] = lv_up;   pb.lu[3] = lo_up;
    for (int i = 0; i < 4; i++) { pb.U[i] = wu + i * WSZ; pb.W[i] = ww + i * WSZ; }
    prep_weff_split<<<dim3(DIM / 256, DIM, 4), 256>>>(pb, scale);

    // 2) QKV projections: batched fp16 2-MMA GEMM
    GemmBatch gqkv;
    gqkv.bu[0] = wu + 0 * WSZ; gqkv.bu[1] = wu + 1 * WSZ; gqkv.bu[2] = wu + 2 * WSZ;
    gqkv.bw[0] = ww + 0 * WSZ; gqkv.bw[1] = ww + 1 * WSZ; gqkv.bw[2] = ww + 2 * WSZ;
    gqkv.bias[0] = bq; gqkv.bias[1] = bk; gqkv.bias[2] = bv;
    gqkv.out[0] = q; gqkv.out[1] = k; gqkv.out[2] = v;
    gemm_hmma<<<dim3(DIM / 128, SEQ / 128, 3), 256, GEMM_SMEM>>>(xu, xw, gqkv);

    // 3) norm+rope -> fp16 U/W (Q pre-scaled); V transpose-split (bf16)
    NormBatch nb;
    nb.X[0] = q; nb.X[1] = k;
    nb.w[0] = nq_w; nb.w[1] = nk_w;
    nb.U[0] = quP; nb.U[1] = kuP;
    nb.W[0] = qwP; nb.W[1] = kwP;
    nb.outscale[0] = 0.08838834764831845f; nb.outscale[1] = 1.0f;
    rmsnorm_rope_split<<<dim3(SEQ, 2), 256>>>(nb, fcos, fsin);
    vtrans_split<<<dim3(SEQ / 32, HD / 32, NH), dim3(32, 8)>>>(v, vthi, vtlo);

    // 4) flash attention: U/W QK + bf16 PV -> fp16 U/W O
    flash_attn_tc<<<dim3(SEQ / 128, NH), 256, FA_SMEM>>>(quP, qwP, kuP, kwP,
                                                         vthi, vtlo, ou, ow);

    // 5) output projection (fp16 2-MMA GEMM)
    GemmBatch go;
    go.bu[0] = wu + 3 * WSZ; go.bu[1] = nullptr; go.bu[2] = nullptr;
    go.bw[0] = ww + 3 * WSZ; go.bw[1] = nullptr; go.bw[2] = nullptr;
    go.bias[0] = bo; go.bias[1] = nullptr; go.bias[2] = nullptr;
    go.out[0] = (float*)d_out; go.out[1] = nullptr; go.out[2] = nullptr;
    gemm_hmma<<<dim3(DIM / 128, SEQ / 128, 1), 256, GEMM_SMEM>>>(ou, ow, go);
}